// round 1
// baseline (speedup 1.0000x reference)
#include <cuda_runtime.h>
#include <cuda_bf16.h>
#include <math.h>

#define T_  512
#define B_  16
#define D_  512
#define H_  8
#define DH_ 64
#define DI_ 2048
#define L_  4
#define SCALE_ (0.125f)   // 1/sqrt(64)
#define NEG_INF_ (-1e9f)

// ------------------------- static device scratch -------------------------
__device__ float g_h   [(size_t)T_*B_*D_];          // current hidden (T,B,D)
__device__ float g_pos [(size_t)2*1024*D_];         // [fw(1024,512); bw(1024,512)]
__device__ float g_wh  [(size_t)T_*B_*3*H_*DH_];    // qkv (T,B,1536)
__device__ float g_rk  [(size_t)2048*D_];           // pos proj (2048,512)
__device__ float g_sc  [(size_t)B_*H_*T_*T_];       // scores (B*H, T, T)
__device__ float g_vec [(size_t)T_*B_*D_];          // attn vec (T,B,512)
__device__ float g_t1  [(size_t)T_*B_*D_];          // temp (T,B,512)
__device__ float g_ff  [(size_t)T_*B_*DI_];         // ff intermediate
__device__ unsigned char g_pad[B_*T_];              // 1 = padding key

// ------------------------- mask build (dtype-robust) -------------------------
__global__ void mask_kernel(const unsigned char* __restrict__ raw, unsigned char* __restrict__ pad)
{
    int idx = blockIdx.x * blockDim.x + threadIdx.x;
    if (idx >= B_ * T_) return;
    unsigned char b0 = raw[0], b1 = raw[1];
    bool m;
    if (b0 == 1 && b1 == 1) {            // bool / uint8
        m = raw[idx] != 0;
    } else if (b0 == 1) {                // int32
        m = ((const int*)raw)[idx] != 0;
    } else {                             // float32
        m = ((const float*)raw)[idx] != 0.0f;
    }
    pad[idx] = m ? 0 : 1;
}

// ------------------------- positional embeddings -------------------------
__global__ void pos_kernel(float* __restrict__ pos)
{
    int idx = blockIdx.x * blockDim.x + threadIdx.x;      // over 2048*512
    if (idx >= 2048 * D_) return;
    int m = idx / D_;
    int k = idx - m * D_;
    int grp = m >> 10;            // 0: fw, 1: bw
    int mm  = m & 1023;
    float p = (grp == 0) ? (float)(T_ - mm) : (float)(mm - T_);
    int kk = (k < 256) ? k : (k - 256);
    float invf = powf(10000.0f, -((float)(2 * kk) / (float)D_));
    float s = p * invf;
    pos[idx] = (k < 256) ? sinf(s) : cosf(s);
}

// ------------------------- layernorm (optionally add, optionally transposed outs) ---------
__global__ __launch_bounds__(256)
void ln_kernel(const float* __restrict__ x, const float* __restrict__ addv,
               const float* __restrict__ g, const float* __restrict__ be,
               float* __restrict__ out_seq, float* __restrict__ outb0,
               float* __restrict__ outb1, int in_bt)
{
    int row = blockIdx.x;              // t*B + b
    int t = row / B_, b = row - t * B_;
    size_t iseq = (size_t)row * D_;
    size_t ibt  = ((size_t)b * T_ + t) * D_;
    const float* px = x + (in_bt ? ibt : iseq);
    int d0 = threadIdx.x, d1 = threadIdx.x + 256;
    float v0 = px[d0], v1 = px[d1];
    if (addv) { v0 += addv[iseq + d0]; v1 += addv[iseq + d1]; }
    float s = v0 + v1;
    float q = v0 * v0 + v1 * v1;
    __shared__ float sh[2][8];
    #pragma unroll
    for (int o = 16; o; o >>= 1) {
        s += __shfl_xor_sync(0xffffffffu, s, o);
        q += __shfl_xor_sync(0xffffffffu, q, o);
    }
    int w = threadIdx.x >> 5, ln = threadIdx.x & 31;
    if (ln == 0) { sh[0][w] = s; sh[1][w] = q; }
    __syncthreads();
    if (threadIdx.x < 32) {
        s = (ln < 8) ? sh[0][ln] : 0.f;
        q = (ln < 8) ? sh[1][ln] : 0.f;
        #pragma unroll
        for (int o = 4; o; o >>= 1) {
            s += __shfl_xor_sync(0xffffffffu, s, o);
            q += __shfl_xor_sync(0xffffffffu, q, o);
        }
        if (ln == 0) { sh[0][0] = s; sh[1][0] = q; }
    }
    __syncthreads();
    float mean = sh[0][0] * (1.0f / 512.0f);
    float var  = sh[1][0] * (1.0f / 512.0f) - mean * mean;
    float r = rsqrtf(var + 1e-6f);
    float y0 = (v0 - mean) * r * g[d0] + be[d0];
    float y1 = (v1 - mean) * r * g[d1] + be[d1];
    out_seq[iseq + d0] = y0; out_seq[iseq + d1] = y1;
    if (outb0) { outb0[ibt + d0] = y0; outb0[ibt + d1] = y1; }
    if (outb1) { outb1[ibt + d0] = y0; outb1[ibt + d1] = y1; }
}

// ------------------------- generic SGEMM: C = A(MxK) @ W(KxN) [+bias][+relu] ---------
__global__ __launch_bounds__(256)
void sgemm_kernel(const float* __restrict__ A, const float* __restrict__ W,
                  const float* __restrict__ bias, float* __restrict__ C,
                  int M, int N, int K, int relu)
{
    __shared__ float As[16][68];
    __shared__ float Bs[16][68];
    int m0 = blockIdx.y * 64, n0 = blockIdx.x * 64;
    int tid = threadIdx.x;
    int ty = tid >> 4, tx = tid & 15;
    float acc[4][4] = {};
    for (int kt = 0; kt < K; kt += 16) {
        #pragma unroll
        for (int l = 0; l < 4; ++l) {
            int e = tid + l * 256;
            int am = e >> 4, ak = e & 15;
            As[ak][am] = A[(size_t)(m0 + am) * K + kt + ak];
            int bk = e >> 6, bn = e & 63;
            Bs[bk][bn] = W[(size_t)(kt + bk) * N + n0 + bn];
        }
        __syncthreads();
        #pragma unroll
        for (int k = 0; k < 16; ++k) {
            float a0 = As[k][ty*4+0], a1 = As[k][ty*4+1], a2 = As[k][ty*4+2], a3 = As[k][ty*4+3];
            float b0 = Bs[k][tx*4+0], b1 = Bs[k][tx*4+1], b2 = Bs[k][tx*4+2], b3 = Bs[k][tx*4+3];
            acc[0][0] += a0*b0; acc[0][1] += a0*b1; acc[0][2] += a0*b2; acc[0][3] += a0*b3;
            acc[1][0] += a1*b0; acc[1][1] += a1*b1; acc[1][2] += a1*b2; acc[1][3] += a1*b3;
            acc[2][0] += a2*b0; acc[2][1] += a2*b1; acc[2][2] += a2*b2; acc[2][3] += a2*b3;
            acc[3][0] += a3*b0; acc[3][1] += a3*b1; acc[3][2] += a3*b2; acc[3][3] += a3*b3;
        }
        __syncthreads();
    }
    #pragma unroll
    for (int i = 0; i < 4; ++i) {
        int row = m0 + ty * 4 + i;
        #pragma unroll
        for (int j = 0; j < 4; ++j) {
            int col = n0 + tx * 4 + j;
            float v = acc[i][j];
            if (bias) v += bias[col];
            if (relu) v = fmaxf(v, 0.0f);
            C[(size_t)row * N + col] = v;
        }
    }
}

// ------------------------- fused AC+BD score kernel -------------------------
// score[z=b*H+n][i][j] = mask ? -1e9 : SCALE * ( (q_i+rwb)·k_j + (q_i+rrb)·rk[j-i+512] )
__global__ __launch_bounds__(256)
void score_kernel(const float* __restrict__ wh, const float* __restrict__ rk,
                  const float* __restrict__ rwb, const float* __restrict__ rrb,
                  const unsigned char* __restrict__ pad, float* __restrict__ sc)
{
    __shared__ float qwT[64][33];   // [kd][i_local]
    __shared__ float qrT[64][33];
    __shared__ float kkT[64][33];   // [kd][j_local]
    __shared__ float rrT[64][65];   // [kd][mloc], mloc in [0,62]
    int z = blockIdx.z;
    int b = z >> 3, n = z & 7;
    int i0 = blockIdx.y * 32, j0 = blockIdx.x * 32;
    int grp = (b >= (B_ / 2)) ? 1 : 0;
    int tid = threadIdx.x;
    const float* rwbn = rwb + n * 64;
    const float* rrbn = rrb + n * 64;

    #pragma unroll
    for (int l = 0; l < 8; ++l) {
        int e = tid + l * 256;           // 2048 elems = 32 rows x 64 kd
        int il = e >> 6, kd = e & 63;
        float qv = wh[((size_t)(i0 + il) * B_ + b) * 1536 + n * 64 + kd];
        qwT[kd][il] = qv + rwbn[kd];
        qrT[kd][il] = qv + rrbn[kd];
        kkT[kd][il] = wh[((size_t)(j0 + il) * B_ + b) * 1536 + 512 + n * 64 + kd];
    }
    for (int e = tid; e < 63 * 64; e += 256) {
        int mloc = e >> 6, kd = e & 63;
        int m = j0 - i0 + 481 + mloc;    // in [1,1023]
        rrT[kd][mloc] = rk[((size_t)(grp * 1024 + m)) * 512 + n * 64 + kd];
    }
    __syncthreads();

    int ty = tid >> 4, tx = tid & 15;
    int base = tx * 2 - ty * 2 + 31;     // mloc for (i=0,j=0) pair
    float a00 = 0.f, a01 = 0.f, a10 = 0.f, a11 = 0.f;
    #pragma unroll
    for (int kd = 0; kd < 64; ++kd) {
        float w0 = qwT[kd][ty*2],   w1 = qwT[kd][ty*2+1];
        float r0 = qrT[kd][ty*2],   r1 = qrT[kd][ty*2+1];
        float k0 = kkT[kd][tx*2],   k1 = kkT[kd][tx*2+1];
        float rm = rrT[kd][base];
        float rp = rrT[kd][base+1];
        float rn = rrT[kd][base-1];
        a00 += w0*k0 + r0*rm;
        a01 += w0*k1 + r0*rp;
        a10 += w1*k0 + r1*rn;
        a11 += w1*k1 + r1*rm;
    }
    const unsigned char* pb = pad + b * T_;
    size_t bz = (size_t)z * T_ * T_;
    int gi = i0 + ty * 2, gj = j0 + tx * 2;
    float v;
    v = pb[gj+0] ? NEG_INF_ : a00 * SCALE_; sc[bz + (size_t)(gi+0)*T_ + gj+0] = v;
    v = pb[gj+1] ? NEG_INF_ : a01 * SCALE_; sc[bz + (size_t)(gi+0)*T_ + gj+1] = v;
    v = pb[gj+0] ? NEG_INF_ : a10 * SCALE_; sc[bz + (size_t)(gi+1)*T_ + gj+0] = v;
    v = pb[gj+1] ? NEG_INF_ : a11 * SCALE_; sc[bz + (size_t)(gi+1)*T_ + gj+1] = v;
}

// ------------------------- softmax over j (warp per row) -------------------------
__global__ __launch_bounds__(256)
void softmax_kernel(float* __restrict__ P)
{
    size_t row = (size_t)blockIdx.x * 8 + (threadIdx.x >> 5);
    int lane = threadIdx.x & 31;
    float* p = P + row * T_;
    float v[16];
    float mx = -3.4e38f;
    #pragma unroll
    for (int i = 0; i < 16; ++i) { v[i] = p[lane + i * 32]; mx = fmaxf(mx, v[i]); }
    #pragma unroll
    for (int o = 16; o; o >>= 1) mx = fmaxf(mx, __shfl_xor_sync(0xffffffffu, mx, o));
    float s = 0.f;
    #pragma unroll
    for (int i = 0; i < 16; ++i) { v[i] = expf(v[i] - mx); s += v[i]; }
    #pragma unroll
    for (int o = 16; o; o >>= 1) s += __shfl_xor_sync(0xffffffffu, s, o);
    float inv = 1.0f / s;
    #pragma unroll
    for (int i = 0; i < 16; ++i) p[lane + i * 32] = v[i] * inv;
}

// ------------------------- AV: vec[i,b,n,:] = sum_j P[z][i][j] * v[j,b,n,:] -----------
__global__ __launch_bounds__(256)
void av_kernel(const float* __restrict__ P, const float* __restrict__ wh, float* __restrict__ vec)
{
    __shared__ float Ps[16][68];   // [j][i]
    __shared__ float Vs[16][68];   // [j][d]
    int z = blockIdx.z;
    int b = z >> 3, n = z & 7;
    int i0 = blockIdx.y * 64;
    const float* Pz = P + (size_t)z * T_ * T_;
    int tid = threadIdx.x;
    int ty = tid >> 4, tx = tid & 15;
    float acc[4][4] = {};
    for (int jt = 0; jt < T_; jt += 16) {
        #pragma unroll
        for (int l = 0; l < 4; ++l) {
            int e = tid + l * 256;
            int pi = e >> 4, pj = e & 15;
            Ps[pj][pi] = Pz[(size_t)(i0 + pi) * T_ + jt + pj];
            int vj = e >> 6, vd = e & 63;
            Vs[vj][vd] = wh[((size_t)(jt + vj) * B_ + b) * 1536 + 1024 + n * 64 + vd];
        }
        __syncthreads();
        #pragma unroll
        for (int k = 0; k < 16; ++k) {
            float a0 = Ps[k][ty*4+0], a1 = Ps[k][ty*4+1], a2 = Ps[k][ty*4+2], a3 = Ps[k][ty*4+3];
            float b0 = Vs[k][tx*4+0], b1 = Vs[k][tx*4+1], b2 = Vs[k][tx*4+2], b3 = Vs[k][tx*4+3];
            acc[0][0] += a0*b0; acc[0][1] += a0*b1; acc[0][2] += a0*b2; acc[0][3] += a0*b3;
            acc[1][0] += a1*b0; acc[1][1] += a1*b1; acc[1][2] += a1*b2; acc[1][3] += a1*b3;
            acc[2][0] += a2*b0; acc[2][1] += a2*b1; acc[2][2] += a2*b2; acc[2][3] += a2*b3;
            acc[3][0] += a3*b0; acc[3][1] += a3*b1; acc[3][2] += a3*b2; acc[3][3] += a3*b3;
        }
        __syncthreads();
    }
    #pragma unroll
    for (int i = 0; i < 4; ++i) {
        size_t rbase = ((size_t)(i0 + ty * 4 + i) * B_ + b) * 512 + n * 64 + tx * 4;
        #pragma unroll
        for (int j = 0; j < 4; ++j) vec[rbase + j] = acc[i][j];
    }
}

// ------------------------- host orchestration -------------------------
static float* symaddr(const void* sym)
{
    void* p = nullptr;
    cudaGetSymbolAddress(&p, sym);
    return (float*)p;
}

extern "C" void kernel_launch(void* const* d_in, const int* in_sizes, int n_in,
                              void* d_out, int out_size)
{
    const float* h_in  = (const float*)d_in[0];
    const void*  mraw  = d_in[1];
    const float* rwb   = (const float*)d_in[2];
    const float* rrb   = (const float*)d_in[3];
    const float* tlg   = (const float*)d_in[4];
    const float* tlb   = (const float*)d_in[5];
    const float* qkvw  = (const float*)d_in[6];
    const float* rnetw = (const float*)d_in[7];
    const float* ow    = (const float*)d_in[8];
    const float* alg   = (const float*)d_in[9];
    const float* alb   = (const float*)d_in[10];
    const float* w1    = (const float*)d_in[11];
    const float* b1    = (const float*)d_in[12];
    const float* w2    = (const float*)d_in[13];
    const float* b2    = (const float*)d_in[14];
    const float* flg   = (const float*)d_in[15];
    const float* flb   = (const float*)d_in[16];
    float* out = (float*)d_out;

    float* p_h   = symaddr(g_h);
    float* p_pos = symaddr(g_pos);
    float* p_wh  = symaddr(g_wh);
    float* p_rk  = symaddr(g_rk);
    float* p_sc  = symaddr(g_sc);
    float* p_vec = symaddr(g_vec);
    float* p_t1  = symaddr(g_t1);
    float* p_ff  = symaddr(g_ff);
    unsigned char* p_pad;
    { void* tmp; cudaGetSymbolAddress(&tmp, g_pad); p_pad = (unsigned char*)tmp; }

    const size_t BTD = (size_t)B_ * T_ * D_;

    mask_kernel<<<(B_*T_ + 255)/256, 256>>>((const unsigned char*)mraw, p_pad);
    pos_kernel<<<(2048*D_ + 255)/256, 256>>>(p_pos);
    // top LN: read (B,T,D), write g_h (T,B,D) and hids[0] at d_out + 1*BTD
    ln_kernel<<<T_*B_, 256>>>(h_in, nullptr, tlg, tlb, p_h, out + BTD, nullptr, 1);

    for (int i = 0; i < L_; ++i) {
        // QKV: (8192,512) @ (512,1536)
        sgemm_kernel<<<dim3(1536/64, (T_*B_)/64), 256>>>(
            p_h, qkvw + (size_t)i * D_ * 1536, nullptr, p_wh, T_*B_, 1536, D_, 0);
        // rk: (2048,512) @ (512,512)
        sgemm_kernel<<<dim3(512/64, 2048/64), 256>>>(
            p_pos, rnetw + (size_t)i * D_ * 512, nullptr, p_rk, 2048, 512, D_, 0);
        // scores (fused AC + rel-shifted BD + mask + scale)
        score_kernel<<<dim3(T_/32, T_/32, B_*H_), 256>>>(p_wh, p_rk, rwb, rrb, p_pad, p_sc);
        // softmax over keys
        softmax_kernel<<<(B_*H_*T_)/8, 256>>>(p_sc);
        // AV
        av_kernel<<<dim3(1, T_/64, B_*H_), 256>>>(p_sc, p_wh, p_vec);
        // O proj: (8192,512) @ (512,512)
        sgemm_kernel<<<dim3(512/64, (T_*B_)/64), 256>>>(
            p_vec, ow + (size_t)i * 512 * D_, nullptr, p_t1, T_*B_, D_, 512, 0);
        // out1 = LN(h + attn)
        ln_kernel<<<T_*B_, 256>>>(p_h, p_t1, alg + i * D_, alb + i * D_, p_h, nullptr, nullptr, 0);
        // FF1: (8192,512) @ (512,2048) + b1, relu
        sgemm_kernel<<<dim3(DI_/64, (T_*B_)/64), 256>>>(
            p_h, w1 + (size_t)i * D_ * DI_, b1 + (size_t)i * DI_, p_ff, T_*B_, DI_, D_, 1);
        // FF2: (8192,2048) @ (2048,512) + b2
        sgemm_kernel<<<dim3(512/64, (T_*B_)/64), 256>>>(
            p_ff, w2 + (size_t)i * DI_ * D_, b2 + (size_t)i * D_, p_t1, T_*B_, D_, DI_, 0);
        // layer out = LN(out1 + ff) -> g_h, hids[i+1], (and final out)
        float* hb0 = out + (size_t)(2 + i) * BTD;
        float* hb1 = (i == L_ - 1) ? out : nullptr;
        ln_kernel<<<T_*B_, 256>>>(p_h, p_t1, flg + i * D_, flb + i * D_, p_h, hb0, hb1, 0);
    }
}

// round 2
// speedup vs baseline: 1.1225x; 1.1225x over previous
#include <cuda_runtime.h>
#include <cuda_bf16.h>
#include <math.h>

#define T_  512
#define B_  16
#define D_  512
#define H_  8
#define DH_ 64
#define DI_ 2048
#define L_  4
#define SCALE_ (0.125f)   // 1/sqrt(64)
#define NEG_INF_ (-1e9f)

// ------------------------- static device scratch -------------------------
__device__ float g_h   [(size_t)T_*B_*D_];          // current hidden (T,B,D)
__device__ float g_pos [(size_t)2*1024*D_];         // [fw(1024,512); bw(1024,512)]
__device__ float g_wh  [(size_t)T_*B_*3*H_*DH_];    // qkv (T,B,1536)
__device__ float g_rk  [(size_t)2048*D_];           // pos proj (2048,512)
__device__ float g_sc  [(size_t)B_*H_*T_*T_];       // scores (B*H, T, T)
__device__ float g_vec [(size_t)T_*B_*D_];          // attn vec (T,B,512)
__device__ float g_t1  [(size_t)T_*B_*D_];          // temp (T,B,512)
__device__ float g_ff  [(size_t)T_*B_*DI_];         // ff intermediate
__device__ unsigned char g_pad[B_*T_];              // 1 = padding key

// ------------------------- bf16 split helpers -------------------------
__device__ __forceinline__ void fsplit(float v, unsigned short& hi, unsigned short& lo)
{
    __nv_bfloat16 h = __float2bfloat16(v);
    float rem = v - __bfloat162float(h);
    __nv_bfloat16 l = __float2bfloat16(rem);
    hi = __bfloat16_as_ushort(h);
    lo = __bfloat16_as_ushort(l);
}

__device__ __forceinline__ void mma16816(float* d, const unsigned* a, const unsigned* b)
{
    asm volatile(
        "mma.sync.aligned.m16n8k16.row.col.f32.bf16.bf16.f32 "
        "{%0,%1,%2,%3},{%4,%5,%6,%7},{%8,%9},{%0,%1,%2,%3};"
        : "+f"(d[0]), "+f"(d[1]), "+f"(d[2]), "+f"(d[3])
        : "r"(a[0]), "r"(a[1]), "r"(a[2]), "r"(a[3]), "r"(b[0]), "r"(b[1]));
}

// ------------------------- mask build (dtype-robust) -------------------------
__global__ void mask_kernel(const unsigned char* __restrict__ raw, unsigned char* __restrict__ pad)
{
    int idx = blockIdx.x * blockDim.x + threadIdx.x;
    if (idx >= B_ * T_) return;
    unsigned char b0 = raw[0], b1 = raw[1];
    bool m;
    if (b0 == 1 && b1 == 1) {            // bool / uint8
        m = raw[idx] != 0;
    } else if (b0 == 1) {                // int32
        m = ((const int*)raw)[idx] != 0;
    } else {                             // float32
        m = ((const float*)raw)[idx] != 0.0f;
    }
    pad[idx] = m ? 0 : 1;
}

// ------------------------- positional embeddings -------------------------
__global__ void pos_kernel(float* __restrict__ pos)
{
    int idx = blockIdx.x * blockDim.x + threadIdx.x;      // over 2048*512
    if (idx >= 2048 * D_) return;
    int m = idx / D_;
    int k = idx - m * D_;
    int grp = m >> 10;            // 0: fw, 1: bw
    int mm  = m & 1023;
    float p = (grp == 0) ? (float)(T_ - mm) : (float)(mm - T_);
    int kk = (k < 256) ? k : (k - 256);
    float invf = powf(10000.0f, -((float)(2 * kk) / (float)D_));
    float s = p * invf;
    pos[idx] = (k < 256) ? sinf(s) : cosf(s);
}

// ------------------------- layernorm (optionally add, optionally transposed outs) ---------
__global__ __launch_bounds__(256)
void ln_kernel(const float* __restrict__ x, const float* __restrict__ addv,
               const float* __restrict__ g, const float* __restrict__ be,
               float* __restrict__ out_seq, float* __restrict__ outb0,
               float* __restrict__ outb1, int in_bt)
{
    int row = blockIdx.x;              // t*B + b
    int t = row / B_, b = row - t * B_;
    size_t iseq = (size_t)row * D_;
    size_t ibt  = ((size_t)b * T_ + t) * D_;
    const float* px = x + (in_bt ? ibt : iseq);
    int d0 = threadIdx.x, d1 = threadIdx.x + 256;
    float v0 = px[d0], v1 = px[d1];
    if (addv) { v0 += addv[iseq + d0]; v1 += addv[iseq + d1]; }
    float s = v0 + v1;
    float q = v0 * v0 + v1 * v1;
    __shared__ float sh[2][8];
    #pragma unroll
    for (int o = 16; o; o >>= 1) {
        s += __shfl_xor_sync(0xffffffffu, s, o);
        q += __shfl_xor_sync(0xffffffffu, q, o);
    }
    int w = threadIdx.x >> 5, ln = threadIdx.x & 31;
    if (ln == 0) { sh[0][w] = s; sh[1][w] = q; }
    __syncthreads();
    if (threadIdx.x < 32) {
        s = (ln < 8) ? sh[0][ln] : 0.f;
        q = (ln < 8) ? sh[1][ln] : 0.f;
        #pragma unroll
        for (int o = 4; o; o >>= 1) {
            s += __shfl_xor_sync(0xffffffffu, s, o);
            q += __shfl_xor_sync(0xffffffffu, q, o);
        }
        if (ln == 0) { sh[0][0] = s; sh[1][0] = q; }
    }
    __syncthreads();
    float mean = sh[0][0] * (1.0f / 512.0f);
    float var  = sh[1][0] * (1.0f / 512.0f) - mean * mean;
    float r = rsqrtf(var + 1e-6f);
    float y0 = (v0 - mean) * r * g[d0] + be[d0];
    float y1 = (v1 - mean) * r * g[d1] + be[d1];
    out_seq[iseq + d0] = y0; out_seq[iseq + d1] = y1;
    if (outb0) { outb0[ibt + d0] = y0; outb0[ibt + d1] = y1; }
    if (outb1) { outb1[ibt + d0] = y0; outb1[ibt + d1] = y1; }
}

// ------------------------- bf16x3 tensor-core GEMM -------------------------
// C(MxN) = A(MxK) @ W(KxN) [+bias][+relu].  M%128==0, N%128==0, K%16==0.
// Block 128x128, 8 warps (2x4), warp 64x32, m16n8k16 fragments, bf16x3 split.
__global__ __launch_bounds__(256)
void gemm_bf16x3(const float* __restrict__ A, const float* __restrict__ W,
                 const float* __restrict__ bias, float* __restrict__ C,
                 int M, int N, int K, int relu)
{
    __shared__ __align__(16) unsigned short Ah[2][128*24], Al[2][128*24];
    __shared__ __align__(16) unsigned short Bh[2][128*24], Bl[2][128*24];

    int m0 = blockIdx.y * 128, n0 = blockIdx.x * 128;
    int tid = threadIdx.x;
    int lane = tid & 31, w = tid >> 5;
    int wm = (w & 1) * 64, wn = (w >> 1) * 32;
    int r = lane >> 2, c = lane & 3;

    float acc[4][4][4];
    #pragma unroll
    for (int i = 0; i < 4; ++i)
        #pragma unroll
        for (int j = 0; j < 4; ++j)
            #pragma unroll
            for (int q = 0; q < 4; ++q) acc[i][j][q] = 0.f;

    float a_st[8], b_st[8];

    // ---- staging addressing ----
    // A: slot = tid + 256*l -> row = slot>>2 (0..127), c4 = (slot&3)*4
    // B: slot = tid + 256*l -> kr = slot>>5 (0..15), n4 = (slot&31)*4
    #define LOAD_TILE(kt)                                                          \
        {                                                                          \
            _Pragma("unroll")                                                      \
            for (int l = 0; l < 2; ++l) {                                          \
                int slot = tid + 256 * l;                                          \
                int row = slot >> 2, c4 = (slot & 3) * 4;                          \
                float4 va = *(const float4*)(A + (size_t)(m0 + row) * K + (kt) + c4); \
                a_st[l*4+0] = va.x; a_st[l*4+1] = va.y;                            \
                a_st[l*4+2] = va.z; a_st[l*4+3] = va.w;                            \
                int kr = slot >> 5, n4 = (slot & 31) * 4;                          \
                float4 vb = *(const float4*)(W + (size_t)((kt) + kr) * N + n0 + n4); \
                b_st[l*4+0] = vb.x; b_st[l*4+1] = vb.y;                            \
                b_st[l*4+2] = vb.z; b_st[l*4+3] = vb.w;                            \
            }                                                                      \
        }

    #define STORE_TILE(st)                                                         \
        {                                                                          \
            _Pragma("unroll")                                                      \
            for (int l = 0; l < 2; ++l) {                                          \
                int slot = tid + 256 * l;                                          \
                int row = slot >> 2, c4 = (slot & 3) * 4;                          \
                unsigned short h[4], lo[4];                                        \
                _Pragma("unroll")                                                  \
                for (int j = 0; j < 4; ++j) fsplit(a_st[l*4+j], h[j], lo[j]);      \
                uint2 ph, pl;                                                      \
                ph.x = (unsigned)h[0] | ((unsigned)h[1] << 16);                    \
                ph.y = (unsigned)h[2] | ((unsigned)h[3] << 16);                    \
                pl.x = (unsigned)lo[0] | ((unsigned)lo[1] << 16);                  \
                pl.y = (unsigned)lo[2] | ((unsigned)lo[3] << 16);                  \
                *(uint2*)&Ah[st][row*24 + c4] = ph;                                \
                *(uint2*)&Al[st][row*24 + c4] = pl;                                \
                int kr = slot >> 5, n4 = (slot & 31) * 4;                          \
                _Pragma("unroll")                                                  \
                for (int j = 0; j < 4; ++j) {                                      \
                    unsigned short bh, bl;                                         \
                    fsplit(b_st[l*4+j], bh, bl);                                   \
                    Bh[st][(n4+j)*24 + kr] = bh;                                   \
                    Bl[st][(n4+j)*24 + kr] = bl;                                   \
                }                                                                  \
            }                                                                      \
        }

    #define COMPUTE(st)                                                            \
        {                                                                          \
            const unsigned* A32h = (const unsigned*)Ah[st];                        \
            const unsigned* A32l = (const unsigned*)Al[st];                        \
            const unsigned* B32h = (const unsigned*)Bh[st];                        \
            const unsigned* B32l = (const unsigned*)Bl[st];                        \
            unsigned ah[4][4], al[4][4];                                           \
            _Pragma("unroll")                                                      \
            for (int mt = 0; mt < 4; ++mt) {                                       \
                int rb = wm + mt * 16 + r;                                         \
                ah[mt][0] = A32h[rb*12 + c];       ah[mt][1] = A32h[(rb+8)*12 + c];    \
                ah[mt][2] = A32h[rb*12 + c + 4];   ah[mt][3] = A32h[(rb+8)*12 + c + 4];\
                al[mt][0] = A32l[rb*12 + c];       al[mt][1] = A32l[(rb+8)*12 + c];    \
                al[mt][2] = A32l[rb*12 + c + 4];   al[mt][3] = A32l[(rb+8)*12 + c + 4];\
            }                                                                      \
            _Pragma("unroll")                                                      \
            for (int nt = 0; nt < 4; ++nt) {                                       \
                int cb = wn + nt * 8 + r;                                          \
                unsigned bh[2], bl[2];                                             \
                bh[0] = B32h[cb*12 + c]; bh[1] = B32h[cb*12 + c + 4];              \
                bl[0] = B32l[cb*12 + c]; bl[1] = B32l[cb*12 + c + 4];              \
                _Pragma("unroll")                                                  \
                for (int mt = 0; mt < 4; ++mt) {                                   \
                    mma16816(acc[mt][nt], ah[mt], bh);                             \
                    mma16816(acc[mt][nt], ah[mt], bl);                             \
                    mma16816(acc[mt][nt], al[mt], bh);                             \
                }                                                                  \
            }                                                                      \
        }

    LOAD_TILE(0);
    STORE_TILE(0);
    __syncthreads();
    int cur = 0;
    for (int kt = 16; kt < K; kt += 16) {
        LOAD_TILE(kt);
        COMPUTE(cur);
        STORE_TILE(cur ^ 1);
        __syncthreads();
        cur ^= 1;
    }
    COMPUTE(cur);

    #undef LOAD_TILE
    #undef STORE_TILE
    #undef COMPUTE

    #pragma unroll
    for (int mt = 0; mt < 4; ++mt) {
        int row = m0 + wm + mt * 16 + r;
        #pragma unroll
        for (int nt = 0; nt < 4; ++nt) {
            int col = n0 + wn + nt * 8 + 2 * c;
            float bb0 = bias ? bias[col] : 0.f;
            float bb1 = bias ? bias[col + 1] : 0.f;
            float v0 = acc[mt][nt][0] + bb0, v1 = acc[mt][nt][1] + bb1;
            float v2 = acc[mt][nt][2] + bb0, v3 = acc[mt][nt][3] + bb1;
            if (relu) { v0 = fmaxf(v0,0.f); v1 = fmaxf(v1,0.f); v2 = fmaxf(v2,0.f); v3 = fmaxf(v3,0.f); }
            float2 w0 = {v0, v1}, w1 = {v2, v3};
            *(float2*)(C + (size_t)row * N + col) = w0;
            *(float2*)(C + (size_t)(row + 8) * N + col) = w1;
        }
    }
}

// ------------------------- fused AC+BD score kernel (FFMA, unchanged) -------------------------
__global__ __launch_bounds__(256)
void score_kernel(const float* __restrict__ wh, const float* __restrict__ rk,
                  const float* __restrict__ rwb, const float* __restrict__ rrb,
                  const unsigned char* __restrict__ pad, float* __restrict__ sc)
{
    __shared__ float qwT[64][33];
    __shared__ float qrT[64][33];
    __shared__ float kkT[64][33];
    __shared__ float rrT[64][65];
    int z = blockIdx.z;
    int b = z >> 3, n = z & 7;
    int i0 = blockIdx.y * 32, j0 = blockIdx.x * 32;
    int grp = (b >= (B_ / 2)) ? 1 : 0;
    int tid = threadIdx.x;
    const float* rwbn = rwb + n * 64;
    const float* rrbn = rrb + n * 64;

    #pragma unroll
    for (int l = 0; l < 8; ++l) {
        int e = tid + l * 256;
        int il = e >> 6, kd = e & 63;
        float qv = wh[((size_t)(i0 + il) * B_ + b) * 1536 + n * 64 + kd];
        qwT[kd][il] = qv + rwbn[kd];
        qrT[kd][il] = qv + rrbn[kd];
        kkT[kd][il] = wh[((size_t)(j0 + il) * B_ + b) * 1536 + 512 + n * 64 + kd];
    }
    for (int e = tid; e < 63 * 64; e += 256) {
        int mloc = e >> 6, kd = e & 63;
        int m = j0 - i0 + 481 + mloc;
        rrT[kd][mloc] = rk[((size_t)(grp * 1024 + m)) * 512 + n * 64 + kd];
    }
    __syncthreads();

    int ty = tid >> 4, tx = tid & 15;
    int base = tx * 2 - ty * 2 + 31;
    float a00 = 0.f, a01 = 0.f, a10 = 0.f, a11 = 0.f;
    #pragma unroll
    for (int kd = 0; kd < 64; ++kd) {
        float w0 = qwT[kd][ty*2],   w1 = qwT[kd][ty*2+1];
        float r0 = qrT[kd][ty*2],   r1 = qrT[kd][ty*2+1];
        float k0 = kkT[kd][tx*2],   k1 = kkT[kd][tx*2+1];
        float rm = rrT[kd][base];
        float rp = rrT[kd][base+1];
        float rn = rrT[kd][base-1];
        a00 += w0*k0 + r0*rm;
        a01 += w0*k1 + r0*rp;
        a10 += w1*k0 + r1*rn;
        a11 += w1*k1 + r1*rm;
    }
    const unsigned char* pb = pad + b * T_;
    size_t bz = (size_t)z * T_ * T_;
    int gi = i0 + ty * 2, gj = j0 + tx * 2;
    float v;
    v = pb[gj+0] ? NEG_INF_ : a00 * SCALE_; sc[bz + (size_t)(gi+0)*T_ + gj+0] = v;
    v = pb[gj+1] ? NEG_INF_ : a01 * SCALE_; sc[bz + (size_t)(gi+0)*T_ + gj+1] = v;
    v = pb[gj+0] ? NEG_INF_ : a10 * SCALE_; sc[bz + (size_t)(gi+1)*T_ + gj+0] = v;
    v = pb[gj+1] ? NEG_INF_ : a11 * SCALE_; sc[bz + (size_t)(gi+1)*T_ + gj+1] = v;
}

// ------------------------- softmax over j (warp per row) -------------------------
__global__ __launch_bounds__(256)
void softmax_kernel(float* __restrict__ P)
{
    size_t row = (size_t)blockIdx.x * 8 + (threadIdx.x >> 5);
    int lane = threadIdx.x & 31;
    float* p = P + row * T_;
    float v[16];
    float mx = -3.4e38f;
    #pragma unroll
    for (int i = 0; i < 16; ++i) { v[i] = p[lane + i * 32]; mx = fmaxf(mx, v[i]); }
    #pragma unroll
    for (int o = 16; o; o >>= 1) mx = fmaxf(mx, __shfl_xor_sync(0xffffffffu, mx, o));
    float s = 0.f;
    #pragma unroll
    for (int i = 0; i < 16; ++i) { v[i] = expf(v[i] - mx); s += v[i]; }
    #pragma unroll
    for (int o = 16; o; o >>= 1) s += __shfl_xor_sync(0xffffffffu, s, o);
    float inv = 1.0f / s;
    #pragma unroll
    for (int i = 0; i < 16; ++i) p[lane + i * 32] = v[i] * inv;
}

// ------------------------- AV via bf16x3 tensor cores -------------------------
// vec[i,b,n,:] = sum_j P[z][i][j] * V[j,b,n,:], z = b*H + n.
// Block: 128 i-rows x 64 d-cols; 8 warps (4x2), warp 32x32.
__global__ __launch_bounds__(256)
void av_bf16x3(const float* __restrict__ P, const float* __restrict__ wh,
               float* __restrict__ vec)
{
    __shared__ __align__(16) unsigned short Ah[2][128*24], Al[2][128*24];
    __shared__ __align__(16) unsigned short Bh[2][64*24],  Bl[2][64*24];

    int i0 = blockIdx.x * 128;
    int z = blockIdx.y;
    int b = z >> 3, n = z & 7;
    const float* Pz = P + (size_t)z * T_ * T_;
    const float* V  = wh + 1024 + n * 64;   // + ((j)*B_ + b)*1536 later

    int tid = threadIdx.x;
    int lane = tid & 31, w = tid >> 5;
    int wm = (w & 3) * 32, wn = (w >> 2) * 32;
    int r = lane >> 2, c = lane & 3;

    float acc[2][4][4];
    #pragma unroll
    for (int i = 0; i < 2; ++i)
        #pragma unroll
        for (int j = 0; j < 4; ++j)
            #pragma unroll
            for (int q = 0; q < 4; ++q) acc[i][j][q] = 0.f;

    float a_st[8], b_st[4];

    #define AV_LOAD(jt)                                                            \
        {                                                                          \
            _Pragma("unroll")                                                      \
            for (int l = 0; l < 2; ++l) {                                          \
                int slot = tid + 256 * l;                                          \
                int row = slot >> 2, c4 = (slot & 3) * 4;                          \
                float4 va = *(const float4*)(Pz + (size_t)(i0 + row) * T_ + (jt) + c4); \
                a_st[l*4+0] = va.x; a_st[l*4+1] = va.y;                            \
                a_st[l*4+2] = va.z; a_st[l*4+3] = va.w;                            \
            }                                                                      \
            {                                                                      \
                int j = tid >> 4, d4 = (tid & 15) * 4;                             \
                float4 vb = *(const float4*)(V + ((size_t)((jt) + j) * B_ + b) * 1536 + d4); \
                b_st[0] = vb.x; b_st[1] = vb.y; b_st[2] = vb.z; b_st[3] = vb.w;    \
            }                                                                      \
        }

    #define AV_STORE(st)                                                           \
        {                                                                          \
            _Pragma("unroll")                                                      \
            for (int l = 0; l < 2; ++l) {                                          \
                int slot = tid + 256 * l;                                          \
                int row = slot >> 2, c4 = (slot & 3) * 4;                          \
                unsigned short h[4], lo[4];                                        \
                _Pragma("unroll")                                                  \
                for (int j = 0; j < 4; ++j) fsplit(a_st[l*4+j], h[j], lo[j]);      \
                uint2 ph, pl;                                                      \
                ph.x = (unsigned)h[0] | ((unsigned)h[1] << 16);                    \
                ph.y = (unsigned)h[2] | ((unsigned)h[3] << 16);                    \
                pl.x = (unsigned)lo[0] | ((unsigned)lo[1] << 16);                  \
                pl.y = (unsigned)lo[2] | ((unsigned)lo[3] << 16);                  \
                *(uint2*)&Ah[st][row*24 + c4] = ph;                                \
                *(uint2*)&Al[st][row*24 + c4] = pl;                                \
            }                                                                      \
            {                                                                      \
                int j = tid >> 4, d4 = (tid & 15) * 4;                             \
                _Pragma("unroll")                                                  \
                for (int q = 0; q < 4; ++q) {                                      \
                    unsigned short bh, bl;                                         \
                    fsplit(b_st[q], bh, bl);                                       \
                    Bh[st][(d4+q)*24 + j] = bh;                                    \
                    Bl[st][(d4+q)*24 + j] = bl;                                    \
                }                                                                  \
            }                                                                      \
        }

    #define AV_COMPUTE(st)                                                         \
        {                                                                          \
            const unsigned* A32h = (const unsigned*)Ah[st];                        \
            const unsigned* A32l = (const unsigned*)Al[st];                        \
            const unsigned* B32h = (const unsigned*)Bh[st];                        \
            const unsigned* B32l = (const unsigned*)Bl[st];                        \
            unsigned ah[2][4], al[2][4];                                           \
            _Pragma("unroll")                                                      \
            for (int mt = 0; mt < 2; ++mt) {                                       \
                int rb = wm + mt * 16 + r;                                         \
                ah[mt][0] = A32h[rb*12 + c];       ah[mt][1] = A32h[(rb+8)*12 + c];    \
                ah[mt][2] = A32h[rb*12 + c + 4];   ah[mt][3] = A32h[(rb+8)*12 + c + 4];\
                al[mt][0] = A32l[rb*12 + c];       al[mt][1] = A32l[(rb+8)*12 + c];    \
                al[mt][2] = A32l[rb*12 + c + 4];   al[mt][3] = A32l[(rb+8)*12 + c + 4];\
            }                                                                      \
            _Pragma("unroll")                                                      \
            for (int nt = 0; nt < 4; ++nt) {                                       \
                int cb = wn + nt * 8 + r;                                          \
                unsigned bh[2], bl[2];                                             \
                bh[0] = B32h[cb*12 + c]; bh[1] = B32h[cb*12 + c + 4];              \
                bl[0] = B32l[cb*12 + c]; bl[1] = B32l[cb*12 + c + 4];              \
                _Pragma("unroll")                                                  \
                for (int mt = 0; mt < 2; ++mt) {                                   \
                    mma16816(acc[mt][nt], ah[mt], bh);                             \
                    mma16816(acc[mt][nt], ah[mt], bl);                             \
                    mma16816(acc[mt][nt], al[mt], bh);                             \
                }                                                                  \
            }                                                                      \
        }

    AV_LOAD(0);
    AV_STORE(0);
    __syncthreads();
    int cur = 0;
    for (int jt = 16; jt < T_; jt += 16) {
        AV_LOAD(jt);
        AV_COMPUTE(cur);
        AV_STORE(cur ^ 1);
        __syncthreads();
        cur ^= 1;
    }
    AV_COMPUTE(cur);

    #undef AV_LOAD
    #undef AV_STORE
    #undef AV_COMPUTE

    #pragma unroll
    for (int mt = 0; mt < 2; ++mt) {
        int row = i0 + wm + mt * 16 + r;
        #pragma unroll
        for (int nt = 0; nt < 4; ++nt) {
            int col = wn + nt * 8 + 2 * c;
            float2 w0 = {acc[mt][nt][0], acc[mt][nt][1]};
            float2 w1 = {acc[mt][nt][2], acc[mt][nt][3]};
            *(float2*)(vec + ((size_t)row * B_ + b) * 512 + n * 64 + col) = w0;
            *(float2*)(vec + ((size_t)(row + 8) * B_ + b) * 512 + n * 64 + col) = w1;
        }
    }
}

// ------------------------- host orchestration -------------------------
static float* symaddr(const void* sym)
{
    void* p = nullptr;
    cudaGetSymbolAddress(&p, sym);
    return (float*)p;
}

extern "C" void kernel_launch(void* const* d_in, const int* in_sizes, int n_in,
                              void* d_out, int out_size)
{
    const float* h_in  = (const float*)d_in[0];
    const void*  mraw  = d_in[1];
    const float* rwb   = (const float*)d_in[2];
    const float* rrb   = (const float*)d_in[3];
    const float* tlg   = (const float*)d_in[4];
    const float* tlb   = (const float*)d_in[5];
    const float* qkvw  = (const float*)d_in[6];
    const float* rnetw = (const float*)d_in[7];
    const float* ow    = (const float*)d_in[8];
    const float* alg   = (const float*)d_in[9];
    const float* alb   = (const float*)d_in[10];
    const float* w1    = (const float*)d_in[11];
    const float* b1    = (const float*)d_in[12];
    const float* w2    = (const float*)d_in[13];
    const float* b2    = (const float*)d_in[14];
    const float* flg   = (const float*)d_in[15];
    const float* flb   = (const float*)d_in[16];
    float* out = (float*)d_out;

    float* p_h   = symaddr(g_h);
    float* p_pos = symaddr(g_pos);
    float* p_wh  = symaddr(g_wh);
    float* p_rk  = symaddr(g_rk);
    float* p_sc  = symaddr(g_sc);
    float* p_vec = symaddr(g_vec);
    float* p_t1  = symaddr(g_t1);
    float* p_ff  = symaddr(g_ff);
    unsigned char* p_pad;
    { void* tmp; cudaGetSymbolAddress(&tmp, g_pad); p_pad = (unsigned char*)tmp; }

    const size_t BTD = (size_t)B_ * T_ * D_;

    mask_kernel<<<(B_*T_ + 255)/256, 256>>>((const unsigned char*)mraw, p_pad);
    pos_kernel<<<(2048*D_ + 255)/256, 256>>>(p_pos);
    ln_kernel<<<T_*B_, 256>>>(h_in, nullptr, tlg, tlb, p_h, out + BTD, nullptr, 1);

    for (int i = 0; i < L_; ++i) {
        // QKV: (8192,512) @ (512,1536)
        gemm_bf16x3<<<dim3(1536/128, (T_*B_)/128), 256>>>(
            p_h, qkvw + (size_t)i * D_ * 1536, nullptr, p_wh, T_*B_, 1536, D_, 0);
        // rk: (2048,512) @ (512,512)
        gemm_bf16x3<<<dim3(512/128, 2048/128), 256>>>(
            p_pos, rnetw + (size_t)i * D_ * 512, nullptr, p_rk, 2048, 512, D_, 0);
        // scores (fused AC + rel-shifted BD + mask + scale)
        score_kernel<<<dim3(T_/32, T_/32, B_*H_), 256>>>(p_wh, p_rk, rwb, rrb, p_pad, p_sc);
        // softmax over keys
        softmax_kernel<<<(B_*H_*T_)/8, 256>>>(p_sc);
        // AV (tensor cores)
        av_bf16x3<<<dim3(T_/128, B_*H_), 256>>>(p_sc, p_wh, p_vec);
        // O proj: (8192,512) @ (512,512)
        gemm_bf16x3<<<dim3(512/128, (T_*B_)/128), 256>>>(
            p_vec, ow + (size_t)i * 512 * D_, nullptr, p_t1, T_*B_, D_, 512, 0);
        // out1 = LN(h + attn)
        ln_kernel<<<T_*B_, 256>>>(p_h, p_t1, alg + i * D_, alb + i * D_, p_h, nullptr, nullptr, 0);
        // FF1: (8192,512) @ (512,2048) + b1, relu
        gemm_bf16x3<<<dim3(DI_/128, (T_*B_)/128), 256>>>(
            p_h, w1 + (size_t)i * D_ * DI_, b1 + (size_t)i * DI_, p_ff, T_*B_, DI_, D_, 1);
        // FF2: (8192,2048) @ (2048,512) + b2
        gemm_bf16x3<<<dim3(512/128, (T_*B_)/128), 256>>>(
            p_ff, w2 + (size_t)i * DI_ * D_, b2 + (size_t)i * D_, p_t1, T_*B_, D_, DI_, 0);
        // layer out = LN(out1 + ff) -> g_h, hids[i+1], (and final out)
        float* hb0 = out + (size_t)(2 + i) * BTD;
        float* hb1 = (i == L_ - 1) ? out : nullptr;
        ln_kernel<<<T_*B_, 256>>>(p_h, p_t1, flg + i * D_, flb + i * D_, p_h, hb0, hb1, 0);
    }
}

// round 3
// speedup vs baseline: 1.6046x; 1.4295x over previous
#include <cuda_runtime.h>
#include <cuda_bf16.h>
#include <math.h>
#include <stdint.h>

#define T_  512
#define B_  16
#define D_  512
#define H_  8
#define DH_ 64
#define DI_ 2048
#define L_  4
#define SCALE_ (0.125f)
#define NEG_INF_ (-1e9f)

typedef __nv_bfloat16 bf16;

// ------------------------- static device scratch -------------------------
__device__ float g_h   [(size_t)T_*B_*D_];
__device__ bf16  g_hh  [(size_t)T_*B_*D_];
__device__ bf16  g_hl  [(size_t)T_*B_*D_];
__device__ bf16  g_posh[(size_t)2048*D_];
__device__ bf16  g_posl[(size_t)2048*D_];
__device__ float g_wh  [(size_t)T_*B_*1536];
__device__ bf16  g_vth [(size_t)B_*H_*DH_*T_];   // V^T: [(b*H+n)*64+d][t]
__device__ bf16  g_vtl [(size_t)B_*H_*DH_*T_];
__device__ float g_rk  [(size_t)2048*D_];
__device__ float g_sc  [(size_t)B_*H_*T_*T_];
__device__ bf16  g_ph  [(size_t)B_*H_*T_*T_];
__device__ bf16  g_pl  [(size_t)B_*H_*T_*T_];
__device__ bf16  g_vech[(size_t)T_*B_*D_];
__device__ bf16  g_vecl[(size_t)T_*B_*D_];
__device__ float g_t1  [(size_t)T_*B_*D_];
__device__ bf16  g_ffh [(size_t)T_*B_*DI_];
__device__ bf16  g_ffl [(size_t)T_*B_*DI_];
__device__ unsigned char g_pad[B_*T_];
// transposed + split weights: [L][N][K]
__device__ bf16 g_qkvT_h[(size_t)L_*1536*512], g_qkvT_l[(size_t)L_*1536*512];
__device__ bf16 g_rkT_h [(size_t)L_*512*512],  g_rkT_l [(size_t)L_*512*512];
__device__ bf16 g_oT_h  [(size_t)L_*512*512],  g_oT_l  [(size_t)L_*512*512];
__device__ bf16 g_w1T_h [(size_t)L_*2048*512], g_w1T_l [(size_t)L_*2048*512];
__device__ bf16 g_w2T_h [(size_t)L_*512*2048], g_w2T_l [(size_t)L_*512*2048];

// ------------------------- helpers -------------------------
__device__ __forceinline__ void fsplit(float v, unsigned short& hi, unsigned short& lo)
{
    bf16 h = __float2bfloat16(v);
    float rem = v - __bfloat162float(h);
    bf16 l = __float2bfloat16(rem);
    hi = __bfloat16_as_ushort(h);
    lo = __bfloat16_as_ushort(l);
}

__device__ __forceinline__ void split2_store(bf16* oh, bf16* ol, size_t idx, float v0, float v1)
{
    unsigned short h0,l0,h1,l1;
    fsplit(v0,h0,l0); fsplit(v1,h1,l1);
    *(unsigned*)(oh + idx) = (unsigned)h0 | ((unsigned)h1 << 16);
    *(unsigned*)(ol + idx) = (unsigned)l0 | ((unsigned)l1 << 16);
}

__device__ __forceinline__ void mma16816(float* d, const unsigned* a, const unsigned* b)
{
    asm volatile(
        "mma.sync.aligned.m16n8k16.row.col.f32.bf16.bf16.f32 "
        "{%0,%1,%2,%3},{%4,%5,%6,%7},{%8,%9},{%0,%1,%2,%3};"
        : "+f"(d[0]), "+f"(d[1]), "+f"(d[2]), "+f"(d[3])
        : "r"(a[0]), "r"(a[1]), "r"(a[2]), "r"(a[3]), "r"(b[0]), "r"(b[1]));
}

__device__ __forceinline__ void cpasync16(uint32_t saddr, const void* gptr)
{
    asm volatile("cp.async.cg.shared.global [%0], [%1], 16;" :: "r"(saddr), "l"(gptr));
}
__device__ __forceinline__ void cpcommit() { asm volatile("cp.async.commit_group;"); }
__device__ __forceinline__ void cpwait0()  { asm volatile("cp.async.wait_group 0;"); }

// ------------------------- weight transpose + split -------------------------
// W: [K][N] fp32 -> oh/ol: [N][K] bf16, per layer z
__global__ __launch_bounds__(256)
void wtrans_kernel(const float* __restrict__ W, bf16* __restrict__ oh, bf16* __restrict__ ol,
                   int K, int N)
{
    __shared__ float t[32][33];
    int z = blockIdx.z;
    const float* Wz = W + (size_t)z * K * N;
    bf16* ohz = oh + (size_t)z * N * K;
    bf16* olz = ol + (size_t)z * N * K;
    int n0 = blockIdx.x * 32, k0 = blockIdx.y * 32;
    int tx = threadIdx.x & 31, ty = threadIdx.x >> 5;
    #pragma unroll
    for (int i = 0; i < 4; ++i)
        t[ty + 8*i][tx] = Wz[(size_t)(k0 + ty + 8*i) * N + n0 + tx];
    __syncthreads();
    #pragma unroll
    for (int i = 0; i < 4; ++i) {
        int n = n0 + ty + 8*i, k = k0 + tx;
        unsigned short h, l;
        fsplit(t[tx][ty + 8*i], h, l);
        ohz[(size_t)n * K + k] = __ushort_as_bfloat16(h);
        olz[(size_t)n * K + k] = __ushort_as_bfloat16(l);
    }
}

// ------------------------- mask build (dtype-robust) -------------------------
__global__ void mask_kernel(const unsigned char* __restrict__ raw, unsigned char* __restrict__ pad)
{
    int idx = blockIdx.x * blockDim.x + threadIdx.x;
    if (idx >= B_ * T_) return;
    unsigned char b0 = raw[0], b1 = raw[1];
    bool m;
    if (b0 == 1 && b1 == 1)      m = raw[idx] != 0;
    else if (b0 == 1)            m = ((const int*)raw)[idx] != 0;
    else                         m = ((const float*)raw)[idx] != 0.0f;
    pad[idx] = m ? 0 : 1;
}

// ------------------------- positional embeddings (split bf16) -------------------------
__global__ void pos_kernel(bf16* __restrict__ ph, bf16* __restrict__ pl)
{
    int idx = blockIdx.x * blockDim.x + threadIdx.x;
    if (idx >= 2048 * D_) return;
    int m = idx / D_;
    int k = idx - m * D_;
    int grp = m >> 10;
    int mm  = m & 1023;
    float p = (grp == 0) ? (float)(T_ - mm) : (float)(mm - T_);
    int kk = (k < 256) ? k : (k - 256);
    float invf = powf(10000.0f, -((float)(2 * kk) / (float)D_));
    float s = p * invf;
    float v = (k < 256) ? sinf(s) : cosf(s);
    unsigned short h, l;
    fsplit(v, h, l);
    ph[idx] = __ushort_as_bfloat16(h);
    pl[idx] = __ushort_as_bfloat16(l);
}

// ------------------------- layernorm -------------------------
__global__ __launch_bounds__(256)
void ln_kernel(const float* __restrict__ x, const float* __restrict__ addv,
               const float* __restrict__ g, const float* __restrict__ be,
               float* __restrict__ out_seq, bf16* __restrict__ outh, bf16* __restrict__ outl,
               float* __restrict__ outb0, float* __restrict__ outb1, int in_bt)
{
    int row = blockIdx.x;
    int t = row / B_, b = row - t * B_;
    size_t iseq = (size_t)row * D_;
    size_t ibt  = ((size_t)b * T_ + t) * D_;
    const float* px = x + (in_bt ? ibt : iseq);
    int d0 = threadIdx.x, d1 = threadIdx.x + 256;
    float v0 = px[d0], v1 = px[d1];
    if (addv) { v0 += addv[iseq + d0]; v1 += addv[iseq + d1]; }
    float s = v0 + v1;
    float q = v0 * v0 + v1 * v1;
    __shared__ float sh[2][8];
    #pragma unroll
    for (int o = 16; o; o >>= 1) {
        s += __shfl_xor_sync(0xffffffffu, s, o);
        q += __shfl_xor_sync(0xffffffffu, q, o);
    }
    int w = threadIdx.x >> 5, ln = threadIdx.x & 31;
    if (ln == 0) { sh[0][w] = s; sh[1][w] = q; }
    __syncthreads();
    if (threadIdx.x < 32) {
        s = (ln < 8) ? sh[0][ln] : 0.f;
        q = (ln < 8) ? sh[1][ln] : 0.f;
        #pragma unroll
        for (int o = 4; o; o >>= 1) {
            s += __shfl_xor_sync(0xffffffffu, s, o);
            q += __shfl_xor_sync(0xffffffffu, q, o);
        }
        if (ln == 0) { sh[0][0] = s; sh[1][0] = q; }
    }
    __syncthreads();
    float mean = sh[0][0] * (1.0f / 512.0f);
    float var  = sh[1][0] * (1.0f / 512.0f) - mean * mean;
    float r = rsqrtf(var + 1e-6f);
    float y0 = (v0 - mean) * r * g[d0] + be[d0];
    float y1 = (v1 - mean) * r * g[d1] + be[d1];
    out_seq[iseq + d0] = y0; out_seq[iseq + d1] = y1;
    unsigned short h0, l0, h1, l1;
    fsplit(y0, h0, l0); fsplit(y1, h1, l1);
    outh[iseq + d0] = __ushort_as_bfloat16(h0); outh[iseq + d1] = __ushort_as_bfloat16(h1);
    outl[iseq + d0] = __ushort_as_bfloat16(l0); outl[iseq + d1] = __ushort_as_bfloat16(l1);
    if (outb0) { outb0[ibt + d0] = y0; outb0[ibt + d1] = y1; }
    if (outb1) { outb1[ibt + d0] = y0; outb1[ibt + d1] = y1; }
}

// ------------------------- GEMM v2: bf16x3, cp.async, K-tile 32 -------------------------
// A: hi/lo [M][K] bf16; B: hi/lo [N][K] bf16 (pre-transposed).
// MODE 0: Cf fp32 (+bias if non-null)
// MODE 1: bias + relu + split bf16 out (row-major)
// MODE 2: Cf fp32 + V^T split for cols >= 1024 (QKV)
// MODE 3: split bf16 out to vec layout ((i*B+b)*512 + n*64 + col), z = blockIdx.z
template<int BM, int BN, int WM, int WN, int MODE>
__global__ void __launch_bounds__(256)
gemm_v2(const bf16* __restrict__ Ah, const bf16* __restrict__ Al,
        const bf16* __restrict__ Bh, const bf16* __restrict__ Bl,
        const float* __restrict__ bias, float* __restrict__ Cf,
        bf16* __restrict__ Oh, bf16* __restrict__ Ol,
        int M, int N, int K, size_t aStrideZ, size_t bStrideZ)
{
    constexpr int MT = WM / 16, NT = WN / 8;
    constexpr int NWM = BM / WM;
    constexpr int NA = BM * 4, NB = BN * 4, TOTAL = 2 * (NA + NB);
    constexpr int SA = BM * 20, SB = BN * 20;
    constexpr int S = 2 * SA + 2 * SB;     // u32 per stage

    extern __shared__ uint32_t smem[];
    uint32_t sbase = (uint32_t)__cvta_generic_to_shared(smem);

    int z = blockIdx.z;
    const bf16* pAh = Ah + (size_t)z * aStrideZ;
    const bf16* pAl = Al + (size_t)z * aStrideZ;
    const bf16* pBh = Bh + (size_t)z * bStrideZ;
    const bf16* pBl = Bl + (size_t)z * bStrideZ;

    int m0 = blockIdx.y * BM, n0 = blockIdx.x * BN;
    int tid = threadIdx.x, lane = tid & 31, w = tid >> 5;
    int wm = (w % NWM) * WM, wn = (w / NWM) * WN;
    int r = lane >> 2, c = lane & 3;

    float acc[MT][NT][4];
    #pragma unroll
    for (int i = 0; i < MT; ++i)
        #pragma unroll
        for (int j = 0; j < NT; ++j)
            #pragma unroll
            for (int q = 0; q < 4; ++q) acc[i][j][q] = 0.f;

    auto prefetch = [&](int kt, int st) {
        uint32_t base = sbase + (uint32_t)st * S * 4;
        #pragma unroll
        for (int l = 0; l < TOTAL / 256; ++l) {
            int q = tid + l * 256;
            const bf16* gp; uint32_t off;
            if (q < NA) {
                int row = q >> 2, seg = q & 3;
                gp = pAh + (size_t)(m0 + row) * K + kt + seg * 8;
                off = row * 20 + seg * 4;
            } else if (q < 2 * NA) {
                int p = q - NA; int row = p >> 2, seg = p & 3;
                gp = pAl + (size_t)(m0 + row) * K + kt + seg * 8;
                off = SA + row * 20 + seg * 4;
            } else if (q < 2 * NA + NB) {
                int p = q - 2 * NA; int row = p >> 2, seg = p & 3;
                gp = pBh + (size_t)(n0 + row) * K + kt + seg * 8;
                off = 2 * SA + row * 20 + seg * 4;
            } else {
                int p = q - 2 * NA - NB; int row = p >> 2, seg = p & 3;
                gp = pBl + (size_t)(n0 + row) * K + kt + seg * 8;
                off = 2 * SA + SB + row * 20 + seg * 4;
            }
            cpasync16(base + off * 4, gp);
        }
        cpcommit();
    };

    auto compute = [&](int st) {
        const uint32_t* AsH = smem + (size_t)st * S;
        const uint32_t* AsL = AsH + SA;
        const uint32_t* BsH = AsH + 2 * SA;
        const uint32_t* BsL = BsH + SB;
        #pragma unroll
        for (int ks = 0; ks < 2; ++ks) {
            int k0 = ks * 8 + c;
            unsigned ah[MT][4], al[MT][4];
            #pragma unroll
            for (int mt = 0; mt < MT; ++mt) {
                int rb = wm + mt * 16 + r;
                ah[mt][0] = AsH[rb*20 + k0];     ah[mt][1] = AsH[(rb+8)*20 + k0];
                ah[mt][2] = AsH[rb*20 + k0 + 4]; ah[mt][3] = AsH[(rb+8)*20 + k0 + 4];
                al[mt][0] = AsL[rb*20 + k0];     al[mt][1] = AsL[(rb+8)*20 + k0];
                al[mt][2] = AsL[rb*20 + k0 + 4]; al[mt][3] = AsL[(rb+8)*20 + k0 + 4];
            }
            #pragma unroll
            for (int nt = 0; nt < NT; ++nt) {
                int cb = wn + nt * 8 + r;
                unsigned bh[2], bl[2];
                bh[0] = BsH[cb*20 + k0]; bh[1] = BsH[cb*20 + k0 + 4];
                bl[0] = BsL[cb*20 + k0]; bl[1] = BsL[cb*20 + k0 + 4];
                #pragma unroll
                for (int mt = 0; mt < MT; ++mt) {
                    mma16816(acc[mt][nt], ah[mt], bh);
                    mma16816(acc[mt][nt], ah[mt], bl);
                    mma16816(acc[mt][nt], al[mt], bh);
                }
            }
        }
    };

    int nk = K / 32;
    prefetch(0, 0);
    for (int i = 0; i < nk; ++i) {
        cpwait0();
        __syncthreads();
        if (i + 1 < nk) prefetch((i + 1) * 32, (i + 1) & 1);
        compute(i & 1);
    }

    // epilogue
    int zb = z >> 3, zn = z & 7;
    #pragma unroll
    for (int mt = 0; mt < MT; ++mt) {
        int row = m0 + wm + mt * 16 + r;
        #pragma unroll
        for (int nt = 0; nt < NT; ++nt) {
            int col = n0 + wn + nt * 8 + 2 * c;
            float v0 = acc[mt][nt][0], v1 = acc[mt][nt][1];
            float v2 = acc[mt][nt][2], v3 = acc[mt][nt][3];
            if (MODE == 0) {
                if (bias) { v0 += bias[col]; v1 += bias[col+1]; v2 += bias[col]; v3 += bias[col+1]; }
                float2 w0 = {v0, v1}, w1 = {v2, v3};
                *(float2*)(Cf + (size_t)row * N + col) = w0;
                *(float2*)(Cf + (size_t)(row + 8) * N + col) = w1;
            } else if (MODE == 1) {
                float bb0 = bias[col], bb1 = bias[col+1];
                v0 = fmaxf(v0 + bb0, 0.f); v1 = fmaxf(v1 + bb1, 0.f);
                v2 = fmaxf(v2 + bb0, 0.f); v3 = fmaxf(v3 + bb1, 0.f);
                split2_store(Oh, Ol, (size_t)row * N + col, v0, v1);
                split2_store(Oh, Ol, (size_t)(row + 8) * N + col, v2, v3);
            } else if (MODE == 2) {
                float2 w0 = {v0, v1}, w1 = {v2, v3};
                *(float2*)(Cf + (size_t)row * N + col) = w0;
                *(float2*)(Cf + (size_t)(row + 8) * N + col) = w1;
                if (col >= 1024) {
                    int dp = col - 1024;
                    int n = dp >> 6, d = dp & 63;
                    {
                        int b = row & 15, t = row >> 4;
                        size_t base = ((size_t)(b * 8 + n) * 64 + d) * 512 + t;
                        unsigned short h, l;
                        fsplit(v0, h, l); Oh[base] = __ushort_as_bfloat16(h); Ol[base] = __ushort_as_bfloat16(l);
                        fsplit(v1, h, l); Oh[base + 512] = __ushort_as_bfloat16(h); Ol[base + 512] = __ushort_as_bfloat16(l);
                    }
                    {
                        int row2 = row + 8;
                        int b = row2 & 15, t = row2 >> 4;
                        size_t base = ((size_t)(b * 8 + n) * 64 + d) * 512 + t;
                        unsigned short h, l;
                        fsplit(v2, h, l); Oh[base] = __ushort_as_bfloat16(h); Ol[base] = __ushort_as_bfloat16(l);
                        fsplit(v3, h, l); Oh[base + 512] = __ushort_as_bfloat16(h); Ol[base + 512] = __ushort_as_bfloat16(l);
                    }
                }
            } else { // MODE 3: vec layout
                size_t i0 = ((size_t)row * B_ + zb) * 512 + zn * 64 + col;
                size_t i1 = ((size_t)(row + 8) * B_ + zb) * 512 + zn * 64 + col;
                split2_store(Oh, Ol, i0, v0, v1);
                split2_store(Oh, Ol, i1, v2, v3);
            }
        }
    }
}

// ------------------------- fused AC+BD score kernel -------------------------
__global__ __launch_bounds__(256)
void score_kernel(const float* __restrict__ wh, const float* __restrict__ rk,
                  const float* __restrict__ rwb, const float* __restrict__ rrb,
                  const unsigned char* __restrict__ pad, float* __restrict__ sc)
{
    __shared__ float qwT[64][33];
    __shared__ float qrT[64][33];
    __shared__ float kkT[64][33];
    __shared__ float rrT[64][65];
    int z = blockIdx.z;
    int b = z >> 3, n = z & 7;
    int i0 = blockIdx.y * 32, j0 = blockIdx.x * 32;
    int grp = (b >= (B_ / 2)) ? 1 : 0;
    int tid = threadIdx.x;
    const float* rwbn = rwb + n * 64;
    const float* rrbn = rrb + n * 64;

    #pragma unroll
    for (int l = 0; l < 8; ++l) {
        int e = tid + l * 256;
        int il = e >> 6, kd = e & 63;
        float qv = wh[((size_t)(i0 + il) * B_ + b) * 1536 + n * 64 + kd];
        qwT[kd][il] = qv + rwbn[kd];
        qrT[kd][il] = qv + rrbn[kd];
        kkT[kd][il] = wh[((size_t)(j0 + il) * B_ + b) * 1536 + 512 + n * 64 + kd];
    }
    for (int e = tid; e < 63 * 64; e += 256) {
        int mloc = e >> 6, kd = e & 63;
        int m = j0 - i0 + 481 + mloc;
        rrT[kd][mloc] = rk[((size_t)(grp * 1024 + m)) * 512 + n * 64 + kd];
    }
    __syncthreads();

    int ty = tid >> 4, tx = tid & 15;
    int base = tx * 2 - ty * 2 + 31;
    float a00 = 0.f, a01 = 0.f, a10 = 0.f, a11 = 0.f;
    #pragma unroll
    for (int kd = 0; kd < 64; ++kd) {
        float w0 = qwT[kd][ty*2],   w1 = qwT[kd][ty*2+1];
        float r0 = qrT[kd][ty*2],   r1 = qrT[kd][ty*2+1];
        float k0 = kkT[kd][tx*2],   k1 = kkT[kd][tx*2+1];
        float rm = rrT[kd][base];
        float rp = rrT[kd][base+1];
        float rn = rrT[kd][base-1];
        a00 += w0*k0 + r0*rm;
        a01 += w0*k1 + r0*rp;
        a10 += w1*k0 + r1*rn;
        a11 += w1*k1 + r1*rm;
    }
    const unsigned char* pb = pad + b * T_;
    size_t bz = (size_t)z * T_ * T_;
    int gi = i0 + ty * 2, gj = j0 + tx * 2;
    float v;
    v = pb[gj+0] ? NEG_INF_ : a00 * SCALE_; sc[bz + (size_t)(gi+0)*T_ + gj+0] = v;
    v = pb[gj+1] ? NEG_INF_ : a01 * SCALE_; sc[bz + (size_t)(gi+0)*T_ + gj+1] = v;
    v = pb[gj+0] ? NEG_INF_ : a10 * SCALE_; sc[bz + (size_t)(gi+1)*T_ + gj+0] = v;
    v = pb[gj+1] ? NEG_INF_ : a11 * SCALE_; sc[bz + (size_t)(gi+1)*T_ + gj+1] = v;
}

// ------------------------- softmax + split (warp per row) -------------------------
__global__ __launch_bounds__(256)
void softmax_split(const float* __restrict__ S, bf16* __restrict__ Ph, bf16* __restrict__ Pl)
{
    size_t row = (size_t)blockIdx.x * 8 + (threadIdx.x >> 5);
    int lane = threadIdx.x & 31;
    const float* p = S + row * T_;
    float v[16];
    float mx = -3.4e38f;
    #pragma unroll
    for (int i = 0; i < 16; ++i) { v[i] = p[lane + i * 32]; mx = fmaxf(mx, v[i]); }
    #pragma unroll
    for (int o = 16; o; o >>= 1) mx = fmaxf(mx, __shfl_xor_sync(0xffffffffu, mx, o));
    float s = 0.f;
    #pragma unroll
    for (int i = 0; i < 16; ++i) { v[i] = expf(v[i] - mx); s += v[i]; }
    #pragma unroll
    for (int o = 16; o; o >>= 1) s += __shfl_xor_sync(0xffffffffu, s, o);
    float inv = 1.0f / s;
    bf16* ph = Ph + row * T_;
    bf16* pl = Pl + row * T_;
    #pragma unroll
    for (int i = 0; i < 16; ++i) {
        unsigned short h, l;
        fsplit(v[i] * inv, h, l);
        ph[lane + i * 32] = __ushort_as_bfloat16(h);
        pl[lane + i * 32] = __ushort_as_bfloat16(l);
    }
}

// ------------------------- host orchestration -------------------------
template <typename Tp>
static Tp* symaddr(const void* sym)
{
    void* p = nullptr;
    cudaGetSymbolAddress(&p, sym);
    return (Tp*)p;
}

extern "C" void kernel_launch(void* const* d_in, const int* in_sizes, int n_in,
                              void* d_out, int out_size)
{
    const float* h_in  = (const float*)d_in[0];
    const void*  mraw  = d_in[1];
    const float* rwb   = (const float*)d_in[2];
    const float* rrb   = (const float*)d_in[3];
    const float* tlg   = (const float*)d_in[4];
    const float* tlb   = (const float*)d_in[5];
    const float* qkvw  = (const float*)d_in[6];
    const float* rnetw = (const float*)d_in[7];
    const float* ow    = (const float*)d_in[8];
    const float* alg   = (const float*)d_in[9];
    const float* alb   = (const float*)d_in[10];
    const float* w1    = (const float*)d_in[11];
    const float* b1    = (const float*)d_in[12];
    const float* w2    = (const float*)d_in[13];
    const float* b2    = (const float*)d_in[14];
    const float* flg   = (const float*)d_in[15];
    const float* flb   = (const float*)d_in[16];
    float* out = (float*)d_out;

    float* p_h    = symaddr<float>(g_h);
    bf16*  p_hh   = symaddr<bf16>(g_hh);
    bf16*  p_hl   = symaddr<bf16>(g_hl);
    bf16*  p_posh = symaddr<bf16>(g_posh);
    bf16*  p_posl = symaddr<bf16>(g_posl);
    float* p_wh   = symaddr<float>(g_wh);
    bf16*  p_vth  = symaddr<bf16>(g_vth);
    bf16*  p_vtl  = symaddr<bf16>(g_vtl);
    float* p_rk   = symaddr<float>(g_rk);
    float* p_sc   = symaddr<float>(g_sc);
    bf16*  p_ph   = symaddr<bf16>(g_ph);
    bf16*  p_pl   = symaddr<bf16>(g_pl);
    bf16*  p_vech = symaddr<bf16>(g_vech);
    bf16*  p_vecl = symaddr<bf16>(g_vecl);
    float* p_t1   = symaddr<float>(g_t1);
    bf16*  p_ffh  = symaddr<bf16>(g_ffh);
    bf16*  p_ffl  = symaddr<bf16>(g_ffl);
    unsigned char* p_pad = symaddr<unsigned char>(g_pad);

    bf16* p_qkvT_h = symaddr<bf16>(g_qkvT_h); bf16* p_qkvT_l = symaddr<bf16>(g_qkvT_l);
    bf16* p_rkT_h  = symaddr<bf16>(g_rkT_h);  bf16* p_rkT_l  = symaddr<bf16>(g_rkT_l);
    bf16* p_oT_h   = symaddr<bf16>(g_oT_h);   bf16* p_oT_l   = symaddr<bf16>(g_oT_l);
    bf16* p_w1T_h  = symaddr<bf16>(g_w1T_h);  bf16* p_w1T_l  = symaddr<bf16>(g_w1T_l);
    bf16* p_w2T_h  = symaddr<bf16>(g_w2T_h);  bf16* p_w2T_l  = symaddr<bf16>(g_w2T_l);

    auto k_mode0 = gemm_v2<128,128,64,32,0>;
    auto k_mode1 = gemm_v2<128,128,64,32,1>;
    auto k_mode2 = gemm_v2<128,128,64,32,2>;
    auto k_av    = gemm_v2<128,64,32,32,3>;
    const int SMEM_BIG = (2*128*20 + 2*128*20) * 4 * 2;   // 81920 B
    const int SMEM_AV  = (2*128*20 + 2*64*20)  * 4 * 2;   // 61440 B
    cudaFuncSetAttribute(k_mode0, cudaFuncAttributeMaxDynamicSharedMemorySize, SMEM_BIG);
    cudaFuncSetAttribute(k_mode1, cudaFuncAttributeMaxDynamicSharedMemorySize, SMEM_BIG);
    cudaFuncSetAttribute(k_mode2, cudaFuncAttributeMaxDynamicSharedMemorySize, SMEM_BIG);
    cudaFuncSetAttribute(k_av,    cudaFuncAttributeMaxDynamicSharedMemorySize, SMEM_AV);

    const size_t BTD = (size_t)B_ * T_ * D_;

    // weights: transpose + split (per type, layers in grid.z)
    wtrans_kernel<<<dim3(1536/32, 512/32, L_), 256>>>(qkvw, p_qkvT_h, p_qkvT_l, 512, 1536);
    wtrans_kernel<<<dim3(512/32, 512/32, L_), 256>>>(rnetw, p_rkT_h, p_rkT_l, 512, 512);
    wtrans_kernel<<<dim3(512/32, 512/32, L_), 256>>>(ow, p_oT_h, p_oT_l, 512, 512);
    wtrans_kernel<<<dim3(2048/32, 512/32, L_), 256>>>(w1, p_w1T_h, p_w1T_l, 512, 2048);
    wtrans_kernel<<<dim3(512/32, 2048/32, L_), 256>>>(w2, p_w2T_h, p_w2T_l, 2048, 512);

    mask_kernel<<<(B_*T_ + 255)/256, 256>>>((const unsigned char*)mraw, p_pad);
    pos_kernel<<<(2048*D_ + 255)/256, 256>>>(p_posh, p_posl);
    ln_kernel<<<T_*B_, 256>>>(h_in, nullptr, tlg, tlb, p_h, p_hh, p_hl, out + BTD, nullptr, 1);

    for (int i = 0; i < L_; ++i) {
        // QKV: fp32 g_wh + V^T split
        k_mode2<<<dim3(1536/128, (T_*B_)/128, 1), 256, SMEM_BIG>>>(
            p_hh, p_hl, p_qkvT_h + (size_t)i*1536*512, p_qkvT_l + (size_t)i*1536*512,
            nullptr, p_wh, p_vth, p_vtl, T_*B_, 1536, 512, 0, 0);
        // rk: fp32
        k_mode0<<<dim3(512/128, 2048/128, 1), 256, SMEM_BIG>>>(
            p_posh, p_posl, p_rkT_h + (size_t)i*512*512, p_rkT_l + (size_t)i*512*512,
            nullptr, p_rk, nullptr, nullptr, 2048, 512, 512, 0, 0);
        // scores
        score_kernel<<<dim3(T_/32, T_/32, B_*H_), 256>>>(p_wh, p_rk, rwb, rrb, p_pad, p_sc);
        // softmax -> bf16 split P
        softmax_split<<<(B_*H_*T_)/8, 256>>>(p_sc, p_ph, p_pl);
        // AV -> vec split
        k_av<<<dim3(1, T_/128, B_*H_), 256, SMEM_AV>>>(
            p_ph, p_pl, p_vth, p_vtl, nullptr, nullptr, p_vech, p_vecl,
            T_, 64, T_, (size_t)T_*T_, (size_t)64*T_);
        // O proj: fp32
        k_mode0<<<dim3(512/128, (T_*B_)/128, 1), 256, SMEM_BIG>>>(
            p_vech, p_vecl, p_oT_h + (size_t)i*512*512, p_oT_l + (size_t)i*512*512,
            nullptr, p_t1, nullptr, nullptr, T_*B_, 512, 512, 0, 0);
        // out1 = LN(h + attn)
        ln_kernel<<<T_*B_, 256>>>(p_h, p_t1, alg + i*D_, alb + i*D_, p_h, p_hh, p_hl,
                                  nullptr, nullptr, 0);
        // FF1: bias+relu -> split
        k_mode1<<<dim3(DI_/128, (T_*B_)/128, 1), 256, SMEM_BIG>>>(
            p_hh, p_hl, p_w1T_h + (size_t)i*2048*512, p_w1T_l + (size_t)i*2048*512,
            b1 + (size_t)i*DI_, nullptr, p_ffh, p_ffl, T_*B_, DI_, 512, 0, 0);
        // FF2: fp32 + bias
        k_mode0<<<dim3(512/128, (T_*B_)/128, 1), 256, SMEM_BIG>>>(
            p_ffh, p_ffl, p_w2T_h + (size_t)i*512*2048, p_w2T_l + (size_t)i*512*2048,
            b2 + (size_t)i*D_, p_t1, nullptr, nullptr, T_*B_, 512, DI_, 0, 0);
        // layer out = LN(out1 + ff)
        float* hb0 = out + (size_t)(2 + i) * BTD;
        float* hb1 = (i == L_ - 1) ? out : nullptr;
        ln_kernel<<<T_*B_, 256>>>(p_h, p_t1, flg + i*D_, flb + i*D_, p_h, p_hh, p_hl,
                                  hb0, hb1, 0);
    }
}

// round 4
// speedup vs baseline: 2.2340x; 1.3922x over previous
#include <cuda_runtime.h>
#include <cuda_bf16.h>
#include <math.h>
#include <stdint.h>

#define T_  512
#define B_  16
#define D_  512
#define H_  8
#define DH_ 64
#define DI_ 2048
#define L_  4
#define SCALE_ (0.125f)
#define NEG_INF_ (-1e9f)

typedef __nv_bfloat16 bf16;

// ------------------------- static device scratch -------------------------
__device__ float g_h   [(size_t)T_*B_*D_];
__device__ bf16  g_hh  [(size_t)T_*B_*D_];
__device__ bf16  g_hl  [(size_t)T_*B_*D_];
__device__ bf16  g_posh[(size_t)2048*D_];
__device__ bf16  g_posl[(size_t)2048*D_];
// per-head attention operand layouts, z = b*8 + n
__device__ bf16  g_qw_h[(size_t)128*512*64], g_qw_l[(size_t)128*512*64]; // [(z)*512+i][d] pre-scaled
__device__ bf16  g_qr_h[(size_t)128*512*64], g_qr_l[(size_t)128*512*64];
__device__ bf16  g_k_h [(size_t)128*512*64], g_k_l [(size_t)128*512*64];
__device__ bf16  g_vth [(size_t)128*64*512], g_vtl [(size_t)128*64*512]; // [(z)*64+d][t]
__device__ bf16  g_rkbf_h[(size_t)2048*512], g_rkbf_l[(size_t)2048*512];
__device__ float g_E   [(size_t)128*512*1024];    // BD expanded: [z][i][m]
__device__ float g_sc  [(size_t)B_*H_*T_*T_];
__device__ bf16  g_ph  [(size_t)B_*H_*T_*T_];
__device__ bf16  g_pl  [(size_t)B_*H_*T_*T_];
__device__ bf16  g_vech[(size_t)T_*B_*D_];
__device__ bf16  g_vecl[(size_t)T_*B_*D_];
__device__ float g_t1  [(size_t)T_*B_*D_];
__device__ bf16  g_ffh [(size_t)T_*B_*DI_];
__device__ bf16  g_ffl [(size_t)T_*B_*DI_];
__device__ unsigned char g_pad[B_*T_];
// transposed + split weights: [L][N][K]
__device__ bf16 g_qkvT_h[(size_t)L_*1536*512], g_qkvT_l[(size_t)L_*1536*512];
__device__ bf16 g_rkT_h [(size_t)L_*512*512],  g_rkT_l [(size_t)L_*512*512];
__device__ bf16 g_oT_h  [(size_t)L_*512*512],  g_oT_l  [(size_t)L_*512*512];
__device__ bf16 g_w1T_h [(size_t)L_*2048*512], g_w1T_l [(size_t)L_*2048*512];
__device__ bf16 g_w2T_h [(size_t)L_*512*2048], g_w2T_l [(size_t)L_*512*2048];

// ------------------------- helpers -------------------------
__device__ __forceinline__ void fsplit(float v, unsigned short& hi, unsigned short& lo)
{
    bf16 h = __float2bfloat16(v);
    float rem = v - __bfloat162float(h);
    bf16 l = __float2bfloat16(rem);
    hi = __bfloat16_as_ushort(h);
    lo = __bfloat16_as_ushort(l);
}

__device__ __forceinline__ void split2_store(bf16* oh, bf16* ol, size_t idx, float v0, float v1)
{
    unsigned short h0,l0,h1,l1;
    fsplit(v0,h0,l0); fsplit(v1,h1,l1);
    *(unsigned*)(oh + idx) = (unsigned)h0 | ((unsigned)h1 << 16);
    *(unsigned*)(ol + idx) = (unsigned)l0 | ((unsigned)l1 << 16);
}

__device__ __forceinline__ void mma16816(float* d, const unsigned* a, const unsigned* b)
{
    asm volatile(
        "mma.sync.aligned.m16n8k16.row.col.f32.bf16.bf16.f32 "
        "{%0,%1,%2,%3},{%4,%5,%6,%7},{%8,%9},{%0,%1,%2,%3};"
        : "+f"(d[0]), "+f"(d[1]), "+f"(d[2]), "+f"(d[3])
        : "r"(a[0]), "r"(a[1]), "r"(a[2]), "r"(a[3]), "r"(b[0]), "r"(b[1]));
}

__device__ __forceinline__ void cpasync16(uint32_t saddr, const void* gptr)
{
    asm volatile("cp.async.cg.shared.global [%0], [%1], 16;" :: "r"(saddr), "l"(gptr));
}
__device__ __forceinline__ void cpcommit() { asm volatile("cp.async.commit_group;"); }
__device__ __forceinline__ void cpwait0()  { asm volatile("cp.async.wait_group 0;"); }

// ------------------------- weight transpose + split -------------------------
__global__ __launch_bounds__(256)
void wtrans_kernel(const float* __restrict__ W, bf16* __restrict__ oh, bf16* __restrict__ ol,
                   int K, int N)
{
    __shared__ float t[32][33];
    int z = blockIdx.z;
    const float* Wz = W + (size_t)z * K * N;
    bf16* ohz = oh + (size_t)z * N * K;
    bf16* olz = ol + (size_t)z * N * K;
    int n0 = blockIdx.x * 32, k0 = blockIdx.y * 32;
    int tx = threadIdx.x & 31, ty = threadIdx.x >> 5;
    #pragma unroll
    for (int i = 0; i < 4; ++i)
        t[ty + 8*i][tx] = Wz[(size_t)(k0 + ty + 8*i) * N + n0 + tx];
    __syncthreads();
    #pragma unroll
    for (int i = 0; i < 4; ++i) {
        int n = n0 + ty + 8*i, k = k0 + tx;
        unsigned short h, l;
        fsplit(t[tx][ty + 8*i], h, l);
        ohz[(size_t)n * K + k] = __ushort_as_bfloat16(h);
        olz[(size_t)n * K + k] = __ushort_as_bfloat16(l);
    }
}

// ------------------------- mask build (dtype-robust) -------------------------
__global__ void mask_kernel(const unsigned char* __restrict__ raw, unsigned char* __restrict__ pad)
{
    int idx = blockIdx.x * blockDim.x + threadIdx.x;
    if (idx >= B_ * T_) return;
    unsigned char b0 = raw[0], b1 = raw[1];
    bool m;
    if (b0 == 1 && b1 == 1)      m = raw[idx] != 0;
    else if (b0 == 1)            m = ((const int*)raw)[idx] != 0;
    else                         m = ((const float*)raw)[idx] != 0.0f;
    pad[idx] = m ? 0 : 1;
}

// ------------------------- positional embeddings (split bf16) -------------------------
__global__ void pos_kernel(bf16* __restrict__ ph, bf16* __restrict__ pl)
{
    int idx = blockIdx.x * blockDim.x + threadIdx.x;
    if (idx >= 2048 * D_) return;
    int m = idx / D_;
    int k = idx - m * D_;
    int grp = m >> 10;
    int mm  = m & 1023;
    float p = (grp == 0) ? (float)(T_ - mm) : (float)(mm - T_);
    int kk = (k < 256) ? k : (k - 256);
    float invf = powf(10000.0f, -((float)(2 * kk) / (float)D_));
    float s = p * invf;
    float v = (k < 256) ? sinf(s) : cosf(s);
    unsigned short h, l;
    fsplit(v, h, l);
    ph[idx] = __ushort_as_bfloat16(h);
    pl[idx] = __ushort_as_bfloat16(l);
}

// ------------------------- layernorm -------------------------
__global__ __launch_bounds__(256)
void ln_kernel(const float* __restrict__ x, const float* __restrict__ addv,
               const float* __restrict__ g, const float* __restrict__ be,
               float* __restrict__ out_seq, bf16* __restrict__ outh, bf16* __restrict__ outl,
               float* __restrict__ outb0, float* __restrict__ outb1, int in_bt)
{
    int row = blockIdx.x;
    int t = row / B_, b = row - t * B_;
    size_t iseq = (size_t)row * D_;
    size_t ibt  = ((size_t)b * T_ + t) * D_;
    const float* px = x + (in_bt ? ibt : iseq);
    int d0 = threadIdx.x, d1 = threadIdx.x + 256;
    float v0 = px[d0], v1 = px[d1];
    if (addv) { v0 += addv[iseq + d0]; v1 += addv[iseq + d1]; }
    float s = v0 + v1;
    float q = v0 * v0 + v1 * v1;
    __shared__ float sh[2][8];
    #pragma unroll
    for (int o = 16; o; o >>= 1) {
        s += __shfl_xor_sync(0xffffffffu, s, o);
        q += __shfl_xor_sync(0xffffffffu, q, o);
    }
    int w = threadIdx.x >> 5, ln = threadIdx.x & 31;
    if (ln == 0) { sh[0][w] = s; sh[1][w] = q; }
    __syncthreads();
    if (threadIdx.x < 32) {
        s = (ln < 8) ? sh[0][ln] : 0.f;
        q = (ln < 8) ? sh[1][ln] : 0.f;
        #pragma unroll
        for (int o = 4; o; o >>= 1) {
            s += __shfl_xor_sync(0xffffffffu, s, o);
            q += __shfl_xor_sync(0xffffffffu, q, o);
        }
        if (ln == 0) { sh[0][0] = s; sh[1][0] = q; }
    }
    __syncthreads();
    float mean = sh[0][0] * (1.0f / 512.0f);
    float var  = sh[1][0] * (1.0f / 512.0f) - mean * mean;
    float r = rsqrtf(var + 1e-6f);
    float y0 = (v0 - mean) * r * g[d0] + be[d0];
    float y1 = (v1 - mean) * r * g[d1] + be[d1];
    out_seq[iseq + d0] = y0; out_seq[iseq + d1] = y1;
    unsigned short h0, l0, h1, l1;
    fsplit(y0, h0, l0); fsplit(y1, h1, l1);
    outh[iseq + d0] = __ushort_as_bfloat16(h0); outh[iseq + d1] = __ushort_as_bfloat16(h1);
    outl[iseq + d0] = __ushort_as_bfloat16(l0); outl[iseq + d1] = __ushort_as_bfloat16(l1);
    if (outb0) { outb0[ibt + d0] = y0; outb0[ibt + d1] = y1; }
    if (outb1) { outb1[ibt + d0] = y0; outb1[ibt + d1] = y1; }
}

// ------------------------- GEMM v3: bf16x3, cp.async, K-tile 32 -------------------------
// MODE 0: Cf fp32 (+bias if non-null)           [O proj, FF2, E gemm]
// MODE 1: bias + relu + split bf16 out          [FF1]
// MODE 2: QKV epilogue (qw/qr/k/vT split)       [QKV]   (bias=rwb, bias2=rrb)
// MODE 3: split bf16 out to vec layout          [AV]
// MODE 4: split bf16 out row-major              [rk]
// MODE 5: + E shift-add + mask -> fp32 scores   [AC]
// BMODE 0: B ptr = Bh + z*bStrideZ; n0 = bx*BN
// BMODE 1: B = rk split selected by z (grp,n); n0 = 384 - m0 + bx*BN (band)
template<int BM, int BN, int WM, int WN, int MODE, int BMODE>
__global__ void __launch_bounds__(256)
gemm_v3(const bf16* __restrict__ Ah, const bf16* __restrict__ Al,
        const bf16* __restrict__ Bh, const bf16* __restrict__ Bl,
        const float* __restrict__ bias, const float* __restrict__ bias2,
        float* __restrict__ Cf, bf16* __restrict__ Oh, bf16* __restrict__ Ol,
        int M, int N, int K, int lda, int ldb,
        size_t aStrideZ, size_t bStrideZ, size_t cStrideZ)
{
    constexpr int MT = WM / 16, NT = WN / 8;
    constexpr int NWM = BM / WM;
    constexpr int NA = BM * 4, NB = BN * 4, TOTAL = 2 * (NA + NB);
    constexpr int SA = BM * 20, SB = BN * 20;
    constexpr int S = 2 * SA + 2 * SB;

    extern __shared__ uint32_t smem[];
    uint32_t sbase = (uint32_t)__cvta_generic_to_shared(smem);

    int z = blockIdx.z;
    const bf16* pAh = Ah + (size_t)z * aStrideZ;
    const bf16* pAl = Al + (size_t)z * aStrideZ;
    const bf16* pBh;
    const bf16* pBl;
    if (BMODE == 1) {
        size_t off = (size_t)(z >> 6) * 1024 * 512 + (size_t)(z & 7) * 64;
        pBh = Bh + off; pBl = Bl + off;
    } else {
        pBh = Bh + (size_t)z * bStrideZ;
        pBl = Bl + (size_t)z * bStrideZ;
    }
    float* pCf = Cf ? Cf + (size_t)z * cStrideZ : Cf;

    int m0 = blockIdx.y * BM;
    int n0 = (BMODE == 1) ? (384 - m0 + blockIdx.x * BN) : (blockIdx.x * BN);
    int tid = threadIdx.x, lane = tid & 31, w = tid >> 5;
    int wm = (w % NWM) * WM, wn = (w / NWM) * WN;
    int r = lane >> 2, c = lane & 3;

    float acc[MT][NT][4];
    #pragma unroll
    for (int i = 0; i < MT; ++i)
        #pragma unroll
        for (int j = 0; j < NT; ++j)
            #pragma unroll
            for (int q = 0; q < 4; ++q) acc[i][j][q] = 0.f;

    auto prefetch = [&](int kt, int st) {
        uint32_t base = sbase + (uint32_t)st * S * 4;
        #pragma unroll
        for (int l = 0; l < TOTAL / 256; ++l) {
            int q = tid + l * 256;
            const bf16* gp; uint32_t off;
            if (q < NA) {
                int row = q >> 2, seg = q & 3;
                gp = pAh + (size_t)(m0 + row) * lda + kt + seg * 8;
                off = row * 20 + seg * 4;
            } else if (q < 2 * NA) {
                int p = q - NA; int row = p >> 2, seg = p & 3;
                gp = pAl + (size_t)(m0 + row) * lda + kt + seg * 8;
                off = SA + row * 20 + seg * 4;
            } else if (q < 2 * NA + NB) {
                int p = q - 2 * NA; int row = p >> 2, seg = p & 3;
                gp = pBh + (size_t)(n0 + row) * ldb + kt + seg * 8;
                off = 2 * SA + row * 20 + seg * 4;
            } else {
                int p = q - 2 * NA - NB; int row = p >> 2, seg = p & 3;
                gp = pBl + (size_t)(n0 + row) * ldb + kt + seg * 8;
                off = 2 * SA + SB + row * 20 + seg * 4;
            }
            cpasync16(base + off * 4, gp);
        }
        cpcommit();
    };

    auto compute = [&](int st) {
        const uint32_t* AsH = smem + (size_t)st * S;
        const uint32_t* AsL = AsH + SA;
        const uint32_t* BsH = AsH + 2 * SA;
        const uint32_t* BsL = BsH + SB;
        #pragma unroll
        for (int ks = 0; ks < 2; ++ks) {
            int k0 = ks * 8 + c;
            unsigned ah[MT][4], al[MT][4];
            #pragma unroll
            for (int mt = 0; mt < MT; ++mt) {
                int rb = wm + mt * 16 + r;
                ah[mt][0] = AsH[rb*20 + k0];     ah[mt][1] = AsH[(rb+8)*20 + k0];
                ah[mt][2] = AsH[rb*20 + k0 + 4]; ah[mt][3] = AsH[(rb+8)*20 + k0 + 4];
                al[mt][0] = AsL[rb*20 + k0];     al[mt][1] = AsL[(rb+8)*20 + k0];
                al[mt][2] = AsL[rb*20 + k0 + 4]; al[mt][3] = AsL[(rb+8)*20 + k0 + 4];
            }
            #pragma unroll
            for (int nt = 0; nt < NT; ++nt) {
                int cb = wn + nt * 8 + r;
                unsigned bh[2], bl[2];
                bh[0] = BsH[cb*20 + k0]; bh[1] = BsH[cb*20 + k0 + 4];
                bl[0] = BsL[cb*20 + k0]; bl[1] = BsL[cb*20 + k0 + 4];
                #pragma unroll
                for (int mt = 0; mt < MT; ++mt) {
                    mma16816(acc[mt][nt], ah[mt], bh);
                    mma16816(acc[mt][nt], ah[mt], bl);
                    mma16816(acc[mt][nt], al[mt], bh);
                }
            }
        }
    };

    int nk = K / 32;
    prefetch(0, 0);
    for (int i = 0; i < nk; ++i) {
        cpwait0();
        __syncthreads();
        if (i + 1 < nk) prefetch((i + 1) * 32, (i + 1) & 1);
        compute(i & 1);
    }

    // ---------------- epilogue ----------------
    int zb = z >> 3, zn = z & 7;
    #pragma unroll
    for (int mt = 0; mt < MT; ++mt) {
        int row = m0 + wm + mt * 16 + r;
        #pragma unroll
        for (int nt = 0; nt < NT; ++nt) {
            int col = n0 + wn + nt * 8 + 2 * c;
            float v0 = acc[mt][nt][0], v1 = acc[mt][nt][1];
            float v2 = acc[mt][nt][2], v3 = acc[mt][nt][3];
            if (MODE == 0) {
                if (bias) { v0 += bias[col]; v1 += bias[col+1]; v2 += bias[col]; v3 += bias[col+1]; }
                float2 w0 = {v0, v1}, w1 = {v2, v3};
                *(float2*)(pCf + (size_t)row * N + col) = w0;
                *(float2*)(pCf + (size_t)(row + 8) * N + col) = w1;
            } else if (MODE == 1) {
                float bb0 = bias[col], bb1 = bias[col+1];
                v0 = fmaxf(v0 + bb0, 0.f); v1 = fmaxf(v1 + bb1, 0.f);
                v2 = fmaxf(v2 + bb0, 0.f); v3 = fmaxf(v3 + bb1, 0.f);
                split2_store(Oh, Ol, (size_t)row * N + col, v0, v1);
                split2_store(Oh, Ol, (size_t)(row + 8) * N + col, v2, v3);
            } else if (MODE == 2) {
                if (col < 512) {
                    int hn = col >> 6, d = col & 63;
                    float rw0 = bias[col], rw1 = bias[col+1];
                    float rr0 = bias2[col], rr1 = bias2[col+1];
                    {
                        int bb = row & 15, tt = row >> 4;
                        size_t base = ((size_t)(bb*8+hn)*512 + tt)*64 + d;
                        split2_store(g_qw_h, g_qw_l, base, (v0+rw0)*SCALE_, (v1+rw1)*SCALE_);
                        split2_store(g_qr_h, g_qr_l, base, (v0+rr0)*SCALE_, (v1+rr1)*SCALE_);
                    }
                    {
                        int r2 = row + 8;
                        int bb = r2 & 15, tt = r2 >> 4;
                        size_t base = ((size_t)(bb*8+hn)*512 + tt)*64 + d;
                        split2_store(g_qw_h, g_qw_l, base, (v2+rw0)*SCALE_, (v3+rw1)*SCALE_);
                        split2_store(g_qr_h, g_qr_l, base, (v2+rr0)*SCALE_, (v3+rr1)*SCALE_);
                    }
                } else if (col < 1024) {
                    int cc = col - 512;
                    int hn = cc >> 6, d = cc & 63;
                    {
                        int bb = row & 15, tt = row >> 4;
                        size_t base = ((size_t)(bb*8+hn)*512 + tt)*64 + d;
                        split2_store(g_k_h, g_k_l, base, v0, v1);
                    }
                    {
                        int r2 = row + 8;
                        int bb = r2 & 15, tt = r2 >> 4;
                        size_t base = ((size_t)(bb*8+hn)*512 + tt)*64 + d;
                        split2_store(g_k_h, g_k_l, base, v2, v3);
                    }
                } else {
                    int dp = col - 1024;
                    int hn = dp >> 6, d = dp & 63;
                    {
                        int bb = row & 15, tt = row >> 4;
                        size_t base = ((size_t)(bb*8+hn)*64 + d)*512 + tt;
                        unsigned short h, l;
                        fsplit(v0, h, l); g_vth[base] = __ushort_as_bfloat16(h); g_vtl[base] = __ushort_as_bfloat16(l);
                        fsplit(v1, h, l); g_vth[base + 512] = __ushort_as_bfloat16(h); g_vtl[base + 512] = __ushort_as_bfloat16(l);
                    }
                    {
                        int r2 = row + 8;
                        int bb = r2 & 15, tt = r2 >> 4;
                        size_t base = ((size_t)(bb*8+hn)*64 + d)*512 + tt;
                        unsigned short h, l;
                        fsplit(v2, h, l); g_vth[base] = __ushort_as_bfloat16(h); g_vtl[base] = __ushort_as_bfloat16(l);
                        fsplit(v3, h, l); g_vth[base + 512] = __ushort_as_bfloat16(h); g_vtl[base + 512] = __ushort_as_bfloat16(l);
                    }
                }
            } else if (MODE == 3) {
                size_t i0x = ((size_t)row * B_ + zb) * 512 + zn * 64 + col;
                size_t i1x = ((size_t)(row + 8) * B_ + zb) * 512 + zn * 64 + col;
                split2_store(Oh, Ol, i0x, v0, v1);
                split2_store(Oh, Ol, i1x, v2, v3);
            } else if (MODE == 4) {
                split2_store(Oh, Ol, (size_t)row * N + col, v0, v1);
                split2_store(Oh, Ol, (size_t)(row + 8) * N + col, v2, v3);
            } else { // MODE 5: AC + E + mask -> scores
                const unsigned char* pb = g_pad + zb * T_;
                const float* Ez = g_E + (size_t)z * 512 * 1024;
                size_t er0 = (size_t)row * 1024 + (col - row) + 512;
                size_t er1 = (size_t)(row + 8) * 1024 + (col - (row + 8)) + 512;
                float e00 = Ez[er0], e01 = Ez[er0 + 1];
                float e10 = Ez[er1], e11 = Ez[er1 + 1];
                unsigned char mk0 = pb[col], mk1 = pb[col + 1];
                v0 = mk0 ? NEG_INF_ : v0 + e00;
                v1 = mk1 ? NEG_INF_ : v1 + e01;
                v2 = mk0 ? NEG_INF_ : v2 + e10;
                v3 = mk1 ? NEG_INF_ : v3 + e11;
                float2 w0 = {v0, v1}, w1 = {v2, v3};
                *(float2*)(pCf + (size_t)row * N + col) = w0;
                *(float2*)(pCf + (size_t)(row + 8) * N + col) = w1;
            }
        }
    }
}

// ------------------------- softmax + split (warp per row) -------------------------
__global__ __launch_bounds__(256)
void softmax_split(const float* __restrict__ S, bf16* __restrict__ Ph, bf16* __restrict__ Pl)
{
    size_t row = (size_t)blockIdx.x * 8 + (threadIdx.x >> 5);
    int lane = threadIdx.x & 31;
    const float* p = S + row * T_;
    float v[16];
    float mx = -3.4e38f;
    #pragma unroll
    for (int i = 0; i < 16; ++i) { v[i] = p[lane + i * 32]; mx = fmaxf(mx, v[i]); }
    #pragma unroll
    for (int o = 16; o; o >>= 1) mx = fmaxf(mx, __shfl_xor_sync(0xffffffffu, mx, o));
    float s = 0.f;
    #pragma unroll
    for (int i = 0; i < 16; ++i) { v[i] = expf(v[i] - mx); s += v[i]; }
    #pragma unroll
    for (int o = 16; o; o >>= 1) s += __shfl_xor_sync(0xffffffffu, s, o);
    float inv = 1.0f / s;
    bf16* ph = Ph + row * T_;
    bf16* pl = Pl + row * T_;
    #pragma unroll
    for (int i = 0; i < 16; ++i) {
        unsigned short h, l;
        fsplit(v[i] * inv, h, l);
        ph[lane + i * 32] = __ushort_as_bfloat16(h);
        pl[lane + i * 32] = __ushort_as_bfloat16(l);
    }
}

// ------------------------- host orchestration -------------------------
template <typename Tp>
static Tp* symaddr(const void* sym)
{
    void* p = nullptr;
    cudaGetSymbolAddress(&p, sym);
    return (Tp*)p;
}

extern "C" void kernel_launch(void* const* d_in, const int* in_sizes, int n_in,
                              void* d_out, int out_size)
{
    const float* h_in  = (const float*)d_in[0];
    const void*  mraw  = d_in[1];
    const float* rwb   = (const float*)d_in[2];
    const float* rrb   = (const float*)d_in[3];
    const float* tlg   = (const float*)d_in[4];
    const float* tlb   = (const float*)d_in[5];
    const float* qkvw  = (const float*)d_in[6];
    const float* rnetw = (const float*)d_in[7];
    const float* ow    = (const float*)d_in[8];
    const float* alg   = (const float*)d_in[9];
    const float* alb   = (const float*)d_in[10];
    const float* w1    = (const float*)d_in[11];
    const float* b1    = (const float*)d_in[12];
    const float* w2    = (const float*)d_in[13];
    const float* b2    = (const float*)d_in[14];
    const float* flg   = (const float*)d_in[15];
    const float* flb   = (const float*)d_in[16];
    float* out = (float*)d_out;

    float* p_h    = symaddr<float>(g_h);
    bf16*  p_hh   = symaddr<bf16>(g_hh);
    bf16*  p_hl   = symaddr<bf16>(g_hl);
    bf16*  p_posh = symaddr<bf16>(g_posh);
    bf16*  p_posl = symaddr<bf16>(g_posl);
    bf16*  p_qw_h = symaddr<bf16>(g_qw_h); bf16* p_qw_l = symaddr<bf16>(g_qw_l);
    bf16*  p_qr_h = symaddr<bf16>(g_qr_h); bf16* p_qr_l = symaddr<bf16>(g_qr_l);
    bf16*  p_k_h  = symaddr<bf16>(g_k_h);  bf16* p_k_l  = symaddr<bf16>(g_k_l);
    bf16*  p_vth  = symaddr<bf16>(g_vth);  bf16* p_vtl  = symaddr<bf16>(g_vtl);
    bf16*  p_rkbf_h = symaddr<bf16>(g_rkbf_h); bf16* p_rkbf_l = symaddr<bf16>(g_rkbf_l);
    float* p_E    = symaddr<float>(g_E);
    float* p_sc   = symaddr<float>(g_sc);
    bf16*  p_ph   = symaddr<bf16>(g_ph);
    bf16*  p_pl   = symaddr<bf16>(g_pl);
    bf16*  p_vech = symaddr<bf16>(g_vech);
    bf16*  p_vecl = symaddr<bf16>(g_vecl);
    float* p_t1   = symaddr<float>(g_t1);
    bf16*  p_ffh  = symaddr<bf16>(g_ffh);
    bf16*  p_ffl  = symaddr<bf16>(g_ffl);
    unsigned char* p_pad = symaddr<unsigned char>(g_pad);

    bf16* p_qkvT_h = symaddr<bf16>(g_qkvT_h); bf16* p_qkvT_l = symaddr<bf16>(g_qkvT_l);
    bf16* p_rkT_h  = symaddr<bf16>(g_rkT_h);  bf16* p_rkT_l  = symaddr<bf16>(g_rkT_l);
    bf16* p_oT_h   = symaddr<bf16>(g_oT_h);   bf16* p_oT_l   = symaddr<bf16>(g_oT_l);
    bf16* p_w1T_h  = symaddr<bf16>(g_w1T_h);  bf16* p_w1T_l  = symaddr<bf16>(g_w1T_l);
    bf16* p_w2T_h  = symaddr<bf16>(g_w2T_h);  bf16* p_w2T_l  = symaddr<bf16>(g_w2T_l);

    auto k_qkv = gemm_v3<128,128,64,32,2,0>;
    auto k_rk  = gemm_v3<128,128,64,32,4,0>;
    auto k_E   = gemm_v3<128,128,64,32,0,1>;
    auto k_ac  = gemm_v3<128,128,64,32,5,0>;
    auto k_av  = gemm_v3<128,64,32,32,3,0>;
    auto k_f32 = gemm_v3<128,128,64,32,0,0>;
    auto k_ff1 = gemm_v3<128,128,64,32,1,0>;
    const int SMEM_BIG = (2*128*20 + 2*128*20) * 4 * 2;
    const int SMEM_AV  = (2*128*20 + 2*64*20)  * 4 * 2;
    cudaFuncSetAttribute(k_qkv, cudaFuncAttributeMaxDynamicSharedMemorySize, SMEM_BIG);
    cudaFuncSetAttribute(k_rk,  cudaFuncAttributeMaxDynamicSharedMemorySize, SMEM_BIG);
    cudaFuncSetAttribute(k_E,   cudaFuncAttributeMaxDynamicSharedMemorySize, SMEM_BIG);
    cudaFuncSetAttribute(k_ac,  cudaFuncAttributeMaxDynamicSharedMemorySize, SMEM_BIG);
    cudaFuncSetAttribute(k_av,  cudaFuncAttributeMaxDynamicSharedMemorySize, SMEM_AV);
    cudaFuncSetAttribute(k_f32, cudaFuncAttributeMaxDynamicSharedMemorySize, SMEM_BIG);
    cudaFuncSetAttribute(k_ff1, cudaFuncAttributeMaxDynamicSharedMemorySize, SMEM_BIG);

    const size_t BTD = (size_t)B_ * T_ * D_;

    wtrans_kernel<<<dim3(1536/32, 512/32, L_), 256>>>(qkvw, p_qkvT_h, p_qkvT_l, 512, 1536);
    wtrans_kernel<<<dim3(512/32, 512/32, L_), 256>>>(rnetw, p_rkT_h, p_rkT_l, 512, 512);
    wtrans_kernel<<<dim3(512/32, 512/32, L_), 256>>>(ow, p_oT_h, p_oT_l, 512, 512);
    wtrans_kernel<<<dim3(2048/32, 512/32, L_), 256>>>(w1, p_w1T_h, p_w1T_l, 512, 2048);
    wtrans_kernel<<<dim3(512/32, 2048/32, L_), 256>>>(w2, p_w2T_h, p_w2T_l, 2048, 512);

    mask_kernel<<<(B_*T_ + 255)/256, 256>>>((const unsigned char*)mraw, p_pad);
    pos_kernel<<<(2048*D_ + 255)/256, 256>>>(p_posh, p_posl);
    ln_kernel<<<T_*B_, 256>>>(h_in, nullptr, tlg, tlb, p_h, p_hh, p_hl, out + BTD, nullptr, 1);

    for (int i = 0; i < L_; ++i) {
        // QKV: epilogue writes qw/qr (pre-scaled), k, vT — all split bf16
        k_qkv<<<dim3(1536/128, (T_*B_)/128, 1), 256, SMEM_BIG>>>(
            p_hh, p_hl, p_qkvT_h + (size_t)i*1536*512, p_qkvT_l + (size_t)i*1536*512,
            rwb, rrb, nullptr, nullptr, nullptr, T_*B_, 1536, 512, 512, 512, 0, 0, 0);
        // rk -> split bf16 [2048][512]
        k_rk<<<dim3(512/128, 2048/128, 1), 256, SMEM_BIG>>>(
            p_posh, p_posl, p_rkT_h + (size_t)i*512*512, p_rkT_l + (size_t)i*512*512,
            nullptr, nullptr, nullptr, p_rkbf_h, p_rkbf_l, 2048, 512, 512, 512, 512, 0, 0, 0);
        // E = qr @ rk^T, band-restricted (5 n-tiles per i-tile)
        k_E<<<dim3(5, 4, 128), 256, SMEM_BIG>>>(
            p_qr_h, p_qr_l, p_rkbf_h, p_rkbf_l,
            nullptr, nullptr, p_E, nullptr, nullptr, 512, 1024, 64, 64, 512,
            (size_t)512*64, 0, (size_t)512*1024);
        // scores = qw @ k^T + E[shift] + mask
        k_ac<<<dim3(4, 4, 128), 256, SMEM_BIG>>>(
            p_qw_h, p_qw_l, p_k_h, p_k_l,
            nullptr, nullptr, p_sc, nullptr, nullptr, 512, 512, 64, 64, 64,
            (size_t)512*64, (size_t)512*64, (size_t)512*512);
        // softmax -> bf16 split P
        softmax_split<<<(B_*H_*T_)/8, 256>>>(p_sc, p_ph, p_pl);
        // AV -> vec split
        k_av<<<dim3(1, T_/128, B_*H_), 256, SMEM_AV>>>(
            p_ph, p_pl, p_vth, p_vtl, nullptr, nullptr, nullptr, p_vech, p_vecl,
            T_, 64, T_, 512, 512, (size_t)T_*T_, (size_t)64*T_, 0);
        // O proj: fp32
        k_f32<<<dim3(512/128, (T_*B_)/128, 1), 256, SMEM_BIG>>>(
            p_vech, p_vecl, p_oT_h + (size_t)i*512*512, p_oT_l + (size_t)i*512*512,
            nullptr, nullptr, p_t1, nullptr, nullptr, T_*B_, 512, 512, 512, 512, 0, 0, 0);
        // out1 = LN(h + attn)
        ln_kernel<<<T_*B_, 256>>>(p_h, p_t1, alg + i*D_, alb + i*D_, p_h, p_hh, p_hl,
                                  nullptr, nullptr, 0);
        // FF1: bias+relu -> split
        k_ff1<<<dim3(DI_/128, (T_*B_)/128, 1), 256, SMEM_BIG>>>(
            p_hh, p_hl, p_w1T_h + (size_t)i*2048*512, p_w1T_l + (size_t)i*2048*512,
            b1 + (size_t)i*DI_, nullptr, nullptr, p_ffh, p_ffl, T_*B_, DI_, 512, 512, 512, 0, 0, 0);
        // FF2: fp32 + bias
        k_f32<<<dim3(512/128, (T_*B_)/128, 1), 256, SMEM_BIG>>>(
            p_ffh, p_ffl, p_w2T_h + (size_t)i*512*2048, p_w2T_l + (size_t)i*512*2048,
            b2 + (size_t)i*D_, nullptr, p_t1, nullptr, nullptr, T_*B_, 512, DI_, 2048, 2048, 0, 0, 0);
        // layer out = LN(out1 + ff)
        float* hb0 = out + (size_t)(2 + i) * BTD;
        float* hb1 = (i == L_ - 1) ? out : nullptr;
        ln_kernel<<<T_*B_, 256>>>(p_h, p_t1, flg + i*D_, flb + i*D_, p_h, p_hh, p_hl,
                                  hb0, hb1, 0);
    }
}

// round 5
// speedup vs baseline: 2.4760x; 1.1083x over previous
#include <cuda_runtime.h>
#include <cuda_bf16.h>
#include <math.h>
#include <stdint.h>

#define T_  512
#define B_  16
#define D_  512
#define H_  8
#define DH_ 64
#define DI_ 2048
#define L_  4
#define SCALE_ (0.125f)
#define NEG_INF_ (-1e9f)

typedef __nv_bfloat16 bf16;

// ------------------------- static device scratch -------------------------
__device__ float g_h   [(size_t)T_*B_*D_];
__device__ bf16  g_hh  [(size_t)T_*B_*D_];
__device__ bf16  g_hl  [(size_t)T_*B_*D_];
__device__ bf16  g_posh[(size_t)2048*D_];
__device__ bf16  g_posl[(size_t)2048*D_];
// per-head attention operands, z = b*8 + n
__device__ bf16  g_qw_h[(size_t)128*512*64], g_qw_l[(size_t)128*512*64]; // pre-scaled
__device__ bf16  g_qr_h[(size_t)128*512*64], g_qr_l[(size_t)128*512*64];
__device__ bf16  g_k_h [(size_t)128*512*64], g_k_l [(size_t)128*512*64];
__device__ bf16  g_vth [(size_t)128*64*512], g_vtl [(size_t)128*64*512]; // [(z)*64+d][t]
__device__ bf16  g_rkbf_h[(size_t)(2048+64)*512], g_rkbf_l[(size_t)(2048+64)*512]; // +64 slack rows
__device__ bf16  g_vech[(size_t)T_*B_*D_];
__device__ bf16  g_vecl[(size_t)T_*B_*D_];
__device__ float g_t1  [(size_t)T_*B_*D_];
__device__ bf16  g_ffh [(size_t)T_*B_*DI_];
__device__ bf16  g_ffl [(size_t)T_*B_*DI_];
__device__ unsigned char g_pad[B_*T_];
// transposed + split weights: [L][N][K]
__device__ bf16 g_qkvT_h[(size_t)L_*1536*512], g_qkvT_l[(size_t)L_*1536*512];
__device__ bf16 g_rkT_h [(size_t)L_*512*512],  g_rkT_l [(size_t)L_*512*512];
__device__ bf16 g_oT_h  [(size_t)L_*512*512],  g_oT_l  [(size_t)L_*512*512];
__device__ bf16 g_w1T_h [(size_t)L_*2048*512], g_w1T_l [(size_t)L_*2048*512];
__device__ bf16 g_w2T_h [(size_t)L_*512*2048], g_w2T_l [(size_t)L_*512*2048];

// ------------------------- helpers -------------------------
__device__ __forceinline__ void fsplit(float v, unsigned short& hi, unsigned short& lo)
{
    bf16 h = __float2bfloat16(v);
    float rem = v - __bfloat162float(h);
    bf16 l = __float2bfloat16(rem);
    hi = __bfloat16_as_ushort(h);
    lo = __bfloat16_as_ushort(l);
}

__device__ __forceinline__ void split2_store(bf16* oh, bf16* ol, size_t idx, float v0, float v1)
{
    unsigned short h0,l0,h1,l1;
    fsplit(v0,h0,l0); fsplit(v1,h1,l1);
    *(unsigned*)(oh + idx) = (unsigned)h0 | ((unsigned)h1 << 16);
    *(unsigned*)(ol + idx) = (unsigned)l0 | ((unsigned)l1 << 16);
}

__device__ __forceinline__ void mma16816(float* d, const unsigned* a, const unsigned* b)
{
    asm volatile(
        "mma.sync.aligned.m16n8k16.row.col.f32.bf16.bf16.f32 "
        "{%0,%1,%2,%3},{%4,%5,%6,%7},{%8,%9},{%0,%1,%2,%3};"
        : "+f"(d[0]), "+f"(d[1]), "+f"(d[2]), "+f"(d[3])
        : "r"(a[0]), "r"(a[1]), "r"(a[2]), "r"(a[3]), "r"(b[0]), "r"(b[1]));
}

__device__ __forceinline__ void cpasync16(uint32_t saddr, const void* gptr)
{
    asm volatile("cp.async.cg.shared.global [%0], [%1], 16;" :: "r"(saddr), "l"(gptr));
}
__device__ __forceinline__ void cpcommit() { asm volatile("cp.async.commit_group;"); }
template<int N> __device__ __forceinline__ void cpwaitN()
{ asm volatile("cp.async.wait_group %0;" :: "n"(N)); }

// ------------------------- weight transpose + split -------------------------
__global__ __launch_bounds__(256)
void wtrans_kernel(const float* __restrict__ W, bf16* __restrict__ oh, bf16* __restrict__ ol,
                   int K, int N)
{
    __shared__ float t[32][33];
    int z = blockIdx.z;
    const float* Wz = W + (size_t)z * K * N;
    bf16* ohz = oh + (size_t)z * N * K;
    bf16* olz = ol + (size_t)z * N * K;
    int n0 = blockIdx.x * 32, k0 = blockIdx.y * 32;
    int tx = threadIdx.x & 31, ty = threadIdx.x >> 5;
    #pragma unroll
    for (int i = 0; i < 4; ++i)
        t[ty + 8*i][tx] = Wz[(size_t)(k0 + ty + 8*i) * N + n0 + tx];
    __syncthreads();
    #pragma unroll
    for (int i = 0; i < 4; ++i) {
        int n = n0 + ty + 8*i, k = k0 + tx;
        unsigned short h, l;
        fsplit(t[tx][ty + 8*i], h, l);
        ohz[(size_t)n * K + k] = __ushort_as_bfloat16(h);
        olz[(size_t)n * K + k] = __ushort_as_bfloat16(l);
    }
}

// ------------------------- mask build (dtype-robust) -------------------------
__global__ void mask_kernel(const unsigned char* __restrict__ raw, unsigned char* __restrict__ pad)
{
    int idx = blockIdx.x * blockDim.x + threadIdx.x;
    if (idx >= B_ * T_) return;
    unsigned char b0 = raw[0], b1 = raw[1];
    bool m;
    if (b0 == 1 && b1 == 1)      m = raw[idx] != 0;
    else if (b0 == 1)            m = ((const int*)raw)[idx] != 0;
    else                         m = ((const float*)raw)[idx] != 0.0f;
    pad[idx] = m ? 0 : 1;
}

// ------------------------- positional embeddings (split bf16) -------------------------
__global__ void pos_kernel(bf16* __restrict__ ph, bf16* __restrict__ pl)
{
    int idx = blockIdx.x * blockDim.x + threadIdx.x;
    if (idx >= 2048 * D_) return;
    int m = idx / D_;
    int k = idx - m * D_;
    int grp = m >> 10;
    int mm  = m & 1023;
    float p = (grp == 0) ? (float)(T_ - mm) : (float)(mm - T_);
    int kk = (k < 256) ? k : (k - 256);
    float invf = powf(10000.0f, -((float)(2 * kk) / (float)D_));
    float s = p * invf;
    float v = (k < 256) ? sinf(s) : cosf(s);
    unsigned short h, l;
    fsplit(v, h, l);
    ph[idx] = __ushort_as_bfloat16(h);
    pl[idx] = __ushort_as_bfloat16(l);
}

// ------------------------- layernorm -------------------------
__global__ __launch_bounds__(256)
void ln_kernel(const float* __restrict__ x, const float* __restrict__ addv,
               const float* __restrict__ g, const float* __restrict__ be,
               float* __restrict__ out_seq, bf16* __restrict__ outh, bf16* __restrict__ outl,
               float* __restrict__ outb0, float* __restrict__ outb1, int in_bt)
{
    int row = blockIdx.x;
    int t = row / B_, b = row - t * B_;
    size_t iseq = (size_t)row * D_;
    size_t ibt  = ((size_t)b * T_ + t) * D_;
    const float* px = x + (in_bt ? ibt : iseq);
    int d0 = threadIdx.x, d1 = threadIdx.x + 256;
    float v0 = px[d0], v1 = px[d1];
    if (addv) { v0 += addv[iseq + d0]; v1 += addv[iseq + d1]; }
    float s = v0 + v1;
    float q = v0 * v0 + v1 * v1;
    __shared__ float sh[2][8];
    #pragma unroll
    for (int o = 16; o; o >>= 1) {
        s += __shfl_xor_sync(0xffffffffu, s, o);
        q += __shfl_xor_sync(0xffffffffu, q, o);
    }
    int w = threadIdx.x >> 5, ln = threadIdx.x & 31;
    if (ln == 0) { sh[0][w] = s; sh[1][w] = q; }
    __syncthreads();
    if (threadIdx.x < 32) {
        s = (ln < 8) ? sh[0][ln] : 0.f;
        q = (ln < 8) ? sh[1][ln] : 0.f;
        #pragma unroll
        for (int o = 4; o; o >>= 1) {
            s += __shfl_xor_sync(0xffffffffu, s, o);
            q += __shfl_xor_sync(0xffffffffu, q, o);
        }
        if (ln == 0) { sh[0][0] = s; sh[1][0] = q; }
    }
    __syncthreads();
    float mean = sh[0][0] * (1.0f / 512.0f);
    float var  = sh[1][0] * (1.0f / 512.0f) - mean * mean;
    float r = rsqrtf(var + 1e-6f);
    float y0 = (v0 - mean) * r * g[d0] + be[d0];
    float y1 = (v1 - mean) * r * g[d1] + be[d1];
    out_seq[iseq + d0] = y0; out_seq[iseq + d1] = y1;
    unsigned short h0, l0, h1, l1;
    fsplit(y0, h0, l0); fsplit(y1, h1, l1);
    outh[iseq + d0] = __ushort_as_bfloat16(h0); outh[iseq + d1] = __ushort_as_bfloat16(h1);
    outl[iseq + d0] = __ushort_as_bfloat16(l0); outl[iseq + d1] = __ushort_as_bfloat16(l1);
    if (outb0) { outb0[ibt + d0] = y0; outb0[ibt + d1] = y1; }
    if (outb1) { outb1[ibt + d0] = y0; outb1[ibt + d1] = y1; }
}

// ------------------------- GEMM v3 (dense layers) -------------------------
// MODE 0: Cf fp32 (+bias);  MODE 1: bias+relu+split;  MODE 2: QKV epilogue;  MODE 4: split row-major
template<int BM, int BN, int WM, int WN, int MODE>
__global__ void __launch_bounds__(256)
gemm_v3(const bf16* __restrict__ Ah, const bf16* __restrict__ Al,
        const bf16* __restrict__ Bh, const bf16* __restrict__ Bl,
        const float* __restrict__ bias, const float* __restrict__ bias2,
        float* __restrict__ Cf, bf16* __restrict__ Oh, bf16* __restrict__ Ol,
        int M, int N, int K)
{
    constexpr int MT = WM / 16, NT = WN / 8;
    constexpr int NWM = BM / WM;
    constexpr int NA = BM * 4, NB = BN * 4, TOTAL = 2 * (NA + NB);
    constexpr int SA = BM * 20, SB = BN * 20;
    constexpr int S = 2 * SA + 2 * SB;

    extern __shared__ uint32_t smem[];
    uint32_t sbase = (uint32_t)__cvta_generic_to_shared(smem);

    int m0 = blockIdx.y * BM, n0 = blockIdx.x * BN;
    int tid = threadIdx.x, lane = tid & 31, w = tid >> 5;
    int wm = (w % NWM) * WM, wn = (w / NWM) * WN;
    int r = lane >> 2, c = lane & 3;

    float acc[MT][NT][4];
    #pragma unroll
    for (int i = 0; i < MT; ++i)
        #pragma unroll
        for (int j = 0; j < NT; ++j)
            #pragma unroll
            for (int q = 0; q < 4; ++q) acc[i][j][q] = 0.f;

    auto prefetch = [&](int kt, int st) {
        uint32_t base = sbase + (uint32_t)st * S * 4;
        #pragma unroll
        for (int l = 0; l < TOTAL / 256; ++l) {
            int q = tid + l * 256;
            const bf16* gp; uint32_t off;
            if (q < NA) {
                int row = q >> 2, seg = q & 3;
                gp = Ah + (size_t)(m0 + row) * K + kt + seg * 8;
                off = row * 20 + seg * 4;
            } else if (q < 2 * NA) {
                int p = q - NA; int row = p >> 2, seg = p & 3;
                gp = Al + (size_t)(m0 + row) * K + kt + seg * 8;
                off = SA + row * 20 + seg * 4;
            } else if (q < 2 * NA + NB) {
                int p = q - 2 * NA; int row = p >> 2, seg = p & 3;
                gp = Bh + (size_t)(n0 + row) * K + kt + seg * 8;
                off = 2 * SA + row * 20 + seg * 4;
            } else {
                int p = q - 2 * NA - NB; int row = p >> 2, seg = p & 3;
                gp = Bl + (size_t)(n0 + row) * K + kt + seg * 8;
                off = 2 * SA + SB + row * 20 + seg * 4;
            }
            cpasync16(base + off * 4, gp);
        }
        cpcommit();
    };

    auto compute = [&](int st) {
        const uint32_t* AsH = smem + (size_t)st * S;
        const uint32_t* AsL = AsH + SA;
        const uint32_t* BsH = AsH + 2 * SA;
        const uint32_t* BsL = BsH + SB;
        #pragma unroll
        for (int ks = 0; ks < 2; ++ks) {
            int k0 = ks * 8 + c;
            unsigned ah[MT][4], al[MT][4];
            #pragma unroll
            for (int mt = 0; mt < MT; ++mt) {
                int rb = wm + mt * 16 + r;
                ah[mt][0] = AsH[rb*20 + k0];     ah[mt][1] = AsH[(rb+8)*20 + k0];
                ah[mt][2] = AsH[rb*20 + k0 + 4]; ah[mt][3] = AsH[(rb+8)*20 + k0 + 4];
                al[mt][0] = AsL[rb*20 + k0];     al[mt][1] = AsL[(rb+8)*20 + k0];
                al[mt][2] = AsL[rb*20 + k0 + 4]; al[mt][3] = AsL[(rb+8)*20 + k0 + 4];
            }
            #pragma unroll
            for (int nt = 0; nt < NT; ++nt) {
                int cb = wn + nt * 8 + r;
                unsigned bh[2], bl[2];
                bh[0] = BsH[cb*20 + k0]; bh[1] = BsH[cb*20 + k0 + 4];
                bl[0] = BsL[cb*20 + k0]; bl[1] = BsL[cb*20 + k0 + 4];
                #pragma unroll
                for (int mt = 0; mt < MT; ++mt) {
                    mma16816(acc[mt][nt], ah[mt], bh);
                    mma16816(acc[mt][nt], ah[mt], bl);
                    mma16816(acc[mt][nt], al[mt], bh);
                }
            }
        }
    };

    int nk = K / 32;
    prefetch(0, 0);
    for (int i = 0; i < nk; ++i) {
        cpwaitN<0>();
        __syncthreads();
        if (i + 1 < nk) prefetch((i + 1) * 32, (i + 1) & 1);
        compute(i & 1);
    }

    #pragma unroll
    for (int mt = 0; mt < MT; ++mt) {
        int row = m0 + wm + mt * 16 + r;
        #pragma unroll
        for (int nt = 0; nt < NT; ++nt) {
            int col = n0 + wn + nt * 8 + 2 * c;
            float v0 = acc[mt][nt][0], v1 = acc[mt][nt][1];
            float v2 = acc[mt][nt][2], v3 = acc[mt][nt][3];
            if (MODE == 0) {
                if (bias) { v0 += bias[col]; v1 += bias[col+1]; v2 += bias[col]; v3 += bias[col+1]; }
                float2 w0 = {v0, v1}, w1 = {v2, v3};
                *(float2*)(Cf + (size_t)row * N + col) = w0;
                *(float2*)(Cf + (size_t)(row + 8) * N + col) = w1;
            } else if (MODE == 1) {
                float bb0 = bias[col], bb1 = bias[col+1];
                v0 = fmaxf(v0 + bb0, 0.f); v1 = fmaxf(v1 + bb1, 0.f);
                v2 = fmaxf(v2 + bb0, 0.f); v3 = fmaxf(v3 + bb1, 0.f);
                split2_store(Oh, Ol, (size_t)row * N + col, v0, v1);
                split2_store(Oh, Ol, (size_t)(row + 8) * N + col, v2, v3);
            } else if (MODE == 2) {
                if (col < 512) {
                    int hn = col >> 6, d = col & 63;
                    float rw0 = bias[col], rw1 = bias[col+1];
                    float rr0 = bias2[col], rr1 = bias2[col+1];
                    {
                        int bb = row & 15, tt = row >> 4;
                        size_t base = ((size_t)(bb*8+hn)*512 + tt)*64 + d;
                        split2_store(g_qw_h, g_qw_l, base, (v0+rw0)*SCALE_, (v1+rw1)*SCALE_);
                        split2_store(g_qr_h, g_qr_l, base, (v0+rr0)*SCALE_, (v1+rr1)*SCALE_);
                    }
                    {
                        int r2 = row + 8;
                        int bb = r2 & 15, tt = r2 >> 4;
                        size_t base = ((size_t)(bb*8+hn)*512 + tt)*64 + d;
                        split2_store(g_qw_h, g_qw_l, base, (v2+rw0)*SCALE_, (v3+rw1)*SCALE_);
                        split2_store(g_qr_h, g_qr_l, base, (v2+rr0)*SCALE_, (v3+rr1)*SCALE_);
                    }
                } else if (col < 1024) {
                    int cc = col - 512;
                    int hn = cc >> 6, d = cc & 63;
                    {
                        int bb = row & 15, tt = row >> 4;
                        size_t base = ((size_t)(bb*8+hn)*512 + tt)*64 + d;
                        split2_store(g_k_h, g_k_l, base, v0, v1);
                    }
                    {
                        int r2 = row + 8;
                        int bb = r2 & 15, tt = r2 >> 4;
                        size_t base = ((size_t)(bb*8+hn)*512 + tt)*64 + d;
                        split2_store(g_k_h, g_k_l, base, v2, v3);
                    }
                } else {
                    int dp = col - 1024;
                    int hn = dp >> 6, d = dp & 63;
                    {
                        int bb = row & 15, tt = row >> 4;
                        size_t base = ((size_t)(bb*8+hn)*64 + d)*512 + tt;
                        unsigned short h, l;
                        fsplit(v0, h, l); g_vth[base] = __ushort_as_bfloat16(h); g_vtl[base] = __ushort_as_bfloat16(l);
                        fsplit(v1, h, l); g_vth[base + 512] = __ushort_as_bfloat16(h); g_vtl[base + 512] = __ushort_as_bfloat16(l);
                    }
                    {
                        int r2 = row + 8;
                        int bb = r2 & 15, tt = r2 >> 4;
                        size_t base = ((size_t)(bb*8+hn)*64 + d)*512 + tt;
                        unsigned short h, l;
                        fsplit(v2, h, l); g_vth[base] = __ushort_as_bfloat16(h); g_vtl[base] = __ushort_as_bfloat16(l);
                        fsplit(v3, h, l); g_vth[base + 512] = __ushort_as_bfloat16(h); g_vtl[base + 512] = __ushort_as_bfloat16(l);
                    }
                }
            } else { // MODE 4
                split2_store(Oh, Ol, (size_t)row * N + col, v0, v1);
                split2_store(Oh, Ol, (size_t)(row + 8) * N + col, v2, v3);
            }
        }
    }
}

// ------------------------- fused attention -------------------------
// arena: S fp32 [64][532 u32] -> in-place P split bf16 (hi @ +0, lo @ +266)
#define ARENA_ROW 532
#define ARENA_U32 (64*ARENA_ROW)                 // 34048
#define STRM_OFF  ARENA_U32
#define TILE_U32  5120                           // 64r x 2chunks x 20 x (hi+lo)
#define VT_TILE_U32 2560                         // 64r x 1chunk x 20 x (hi+lo)
#define QBUF_OFF  (STRM_OFF + 2*TILE_U32)        // 44288
#define ATTN_SMEM_U32 (QBUF_OFF + TILE_U32)      // 49408
#define ATTN_SMEM_BYTES (ATTN_SMEM_U32*4)        // 197632

__device__ __forceinline__ void load_tile64x64(uint32_t sb, const bf16* gh, const bf16* gl,
                                               int r0, int ld)
{
    int tid = threadIdx.x;
    #pragma unroll
    for (int l = 0; l < 4; ++l) {
        int q = tid + l*256;
        int comp = q >> 9, p = q & 511;
        int row = p >> 3, seg = p & 7;
        int kc = seg >> 2, u = (seg & 3) * 4;
        const bf16* g = (comp ? gl : gh) + (size_t)(r0 + row) * ld + seg * 8;
        uint32_t off = (uint32_t)(comp * 2560 + kc * 1280 + row * 20 + u);
        cpasync16(sb + off * 4, g);
    }
}

__device__ __forceinline__ void load_tile64x32(uint32_t sb, const bf16* gh, const bf16* gl,
                                               int c0, int ld)
{
    int tid = threadIdx.x;
    #pragma unroll
    for (int l = 0; l < 2; ++l) {
        int q = tid + l*256;
        int comp = q >> 8, p = q & 255;
        int row = p >> 2, seg = p & 3;
        const bf16* g = (comp ? gl : gh) + (size_t)row * ld + c0 + seg * 8;
        uint32_t off = (uint32_t)(comp * 1280 + row * 20 + seg * 4);
        cpasync16(sb + off * 4, g);
    }
}

// 32x16 warp tile over one 64-col tile; K=64 (2 chunks)
__device__ __forceinline__ void mma_qt(float acc[2][2][4], const uint32_t* __restrict__ sm,
                                       int qoff, int toff, int wm, int wn, int r, int c)
{
    #pragma unroll
    for (int kc = 0; kc < 2; ++kc) {
        const uint32_t* QH = sm + qoff + kc*1280;
        const uint32_t* QL = QH + 2560;
        const uint32_t* TH = sm + toff + kc*1280;
        const uint32_t* TL = TH + 2560;
        #pragma unroll
        for (int ks = 0; ks < 2; ++ks) {
            int k0 = ks * 8 + c;
            unsigned ah[2][4], al[2][4];
            #pragma unroll
            for (int mt = 0; mt < 2; ++mt) {
                int rb = wm + mt * 16 + r;
                ah[mt][0] = QH[rb*20 + k0];     ah[mt][1] = QH[(rb+8)*20 + k0];
                ah[mt][2] = QH[rb*20 + k0 + 4]; ah[mt][3] = QH[(rb+8)*20 + k0 + 4];
                al[mt][0] = QL[rb*20 + k0];     al[mt][1] = QL[(rb+8)*20 + k0];
                al[mt][2] = QL[rb*20 + k0 + 4]; al[mt][3] = QL[(rb+8)*20 + k0 + 4];
            }
            #pragma unroll
            for (int nt = 0; nt < 2; ++nt) {
                int cb = wn + nt * 8 + r;
                unsigned bh[2] = { TH[cb*20 + k0], TH[cb*20 + k0 + 4] };
                unsigned bl[2] = { TL[cb*20 + k0], TL[cb*20 + k0 + 4] };
                #pragma unroll
                for (int mt = 0; mt < 2; ++mt) {
                    mma16816(acc[mt][nt], ah[mt], bh);
                    mma16816(acc[mt][nt], ah[mt], bl);
                    mma16816(acc[mt][nt], al[mt], bh);
                }
            }
        }
    }
}

__global__ __launch_bounds__(256)
void attn_fused(const bf16* __restrict__ qwh, const bf16* __restrict__ qwl,
                const bf16* __restrict__ qrh, const bf16* __restrict__ qrl,
                const bf16* __restrict__ kh,  const bf16* __restrict__ kl,
                const bf16* __restrict__ rkh, const bf16* __restrict__ rkl,
                const bf16* __restrict__ vth, const bf16* __restrict__ vtl,
                const unsigned char* __restrict__ pad,
                bf16* __restrict__ vech, bf16* __restrict__ vecl)
{
    extern __shared__ uint32_t sm[];
    float* Sf = (float*)sm;
    uint32_t sb = (uint32_t)__cvta_generic_to_shared(sm);

    int i0 = blockIdx.x * 64;
    int z = blockIdx.y;
    int zb = z >> 3, zn = z & 7;
    int grp = (zb >= 8) ? 1 : 0;
    int tid = threadIdx.x, lane = tid & 31, w = tid >> 5;
    int wm = (w & 1) * 32, wn = (w >> 1) * 16;
    int r = lane >> 2, c = lane & 3;

    const size_t zoff = (size_t)z * 512 * 64;
    const bf16* pqwh = qwh + zoff; const bf16* pqwl = qwl + zoff;
    const bf16* pqrh = qrh + zoff; const bf16* pqrl = qrl + zoff;
    const bf16* pkh  = kh  + zoff; const bf16* pkl  = kl  + zoff;
    const bf16* pvth = vth + zoff; const bf16* pvtl = vtl + zoff;
    int m_lo = 449 - i0;
    const bf16* prkh = rkh + ((size_t)(grp*1024 + m_lo)) * 512 + zn * 64;
    const bf16* prkl = rkl + ((size_t)(grp*1024 + m_lo)) * 512 + zn * 64;

    // ---- Phase A: S = qw @ k^T ----
    load_tile64x64(sb + QBUF_OFF*4, pqwh, pqwl, i0, 64);
    load_tile64x64(sb + STRM_OFF*4, pkh, pkl, 0, 64);
    cpcommit();
    for (int jt = 0; jt < 8; ++jt) {
        if (jt < 7) {
            load_tile64x64(sb + (STRM_OFF + ((jt+1)&1)*TILE_U32)*4, pkh, pkl, (jt+1)*64, 64);
            cpcommit();
            cpwaitN<1>();
        } else cpwaitN<0>();
        __syncthreads();
        float acc[2][2][4] = {};
        mma_qt(acc, sm, QBUF_OFF, STRM_OFF + (jt&1)*TILE_U32, wm, wn, r, c);
        #pragma unroll
        for (int mt = 0; mt < 2; ++mt) {
            int il = wm + mt*16 + r;
            #pragma unroll
            for (int nt = 0; nt < 2; ++nt) {
                int j = jt*64 + wn + nt*8 + 2*c;
                *(float2*)(Sf + il*ARENA_ROW + j)     = make_float2(acc[mt][nt][0], acc[mt][nt][1]);
                *(float2*)(Sf + (il+8)*ARENA_ROW + j) = make_float2(acc[mt][nt][2], acc[mt][nt][3]);
            }
        }
        __syncthreads();
    }

    // ---- Phase B: E = qr @ rk_band^T, scatter-add into S ----
    load_tile64x64(sb + QBUF_OFF*4, pqrh, pqrl, i0, 64);
    load_tile64x64(sb + STRM_OFF*4, prkh, prkl, 0, 512);
    cpcommit();
    for (int mt9 = 0; mt9 < 9; ++mt9) {
        if (mt9 < 8) {
            load_tile64x64(sb + (STRM_OFF + ((mt9+1)&1)*TILE_U32)*4, prkh, prkl, (mt9+1)*64, 512);
            cpcommit();
            cpwaitN<1>();
        } else cpwaitN<0>();
        __syncthreads();
        float acc[2][2][4] = {};
        mma_qt(acc, sm, QBUF_OFF, STRM_OFF + (mt9&1)*TILE_U32, wm, wn, r, c);
        #pragma unroll
        for (int mt = 0; mt < 2; ++mt) {
            #pragma unroll
            for (int nt = 0; nt < 2; ++nt) {
                int mloc = mt9*64 + wn + nt*8 + 2*c;
                int il = wm + mt*16 + r;
                int j = mloc + il - 63;
                if (j >= 0   && j < 512)   Sf[il*ARENA_ROW + j]       += acc[mt][nt][0];
                if (j+1 >= 0 && j+1 < 512) Sf[il*ARENA_ROW + j + 1]   += acc[mt][nt][1];
                int il2 = il + 8;
                int j2 = mloc + il2 - 63;
                if (j2 >= 0   && j2 < 512)   Sf[il2*ARENA_ROW + j2]     += acc[mt][nt][2];
                if (j2+1 >= 0 && j2+1 < 512) Sf[il2*ARENA_ROW + j2 + 1] += acc[mt][nt][3];
            }
        }
        __syncthreads();
    }

    // ---- Phase C: mask + softmax + in-place split-P ----
    {
        const unsigned char* pb = pad + zb * T_;
        for (int rr = 0; rr < 8; ++rr) {
            int il = w*8 + rr;
            float* row = Sf + il*ARENA_ROW;
            float vv[16];
            #pragma unroll
            for (int q4 = 0; q4 < 4; ++q4) {
                int jb = (lane + 32*q4) * 4;
                float4 t = *(float4*)(row + jb);
                unsigned pm = *(const unsigned*)(pb + jb);
                vv[q4*4+0] = (pm & 0xffu)        ? NEG_INF_ : t.x;
                vv[q4*4+1] = (pm & 0xff00u)      ? NEG_INF_ : t.y;
                vv[q4*4+2] = (pm & 0xff0000u)    ? NEG_INF_ : t.z;
                vv[q4*4+3] = (pm & 0xff000000u)  ? NEG_INF_ : t.w;
            }
            float mx = vv[0];
            #pragma unroll
            for (int i = 1; i < 16; ++i) mx = fmaxf(mx, vv[i]);
            #pragma unroll
            for (int o = 16; o; o >>= 1) mx = fmaxf(mx, __shfl_xor_sync(0xffffffffu, mx, o));
            float s = 0.f;
            #pragma unroll
            for (int i = 0; i < 16; ++i) { vv[i] = expf(vv[i] - mx); s += vv[i]; }
            #pragma unroll
            for (int o = 16; o; o >>= 1) s += __shfl_xor_sync(0xffffffffu, s, o);
            float inv = 1.0f / s;
            uint32_t* rh = sm + il*ARENA_ROW;
            uint32_t* rl = rh + 266;
            #pragma unroll
            for (int q4 = 0; q4 < 4; ++q4) {
                int jj = (lane + 32*q4) * 2;
                unsigned short h0,l0,h1,l1,h2,l2,h3,l3;
                fsplit(vv[q4*4+0]*inv, h0, l0);
                fsplit(vv[q4*4+1]*inv, h1, l1);
                fsplit(vv[q4*4+2]*inv, h2, l2);
                fsplit(vv[q4*4+3]*inv, h3, l3);
                uint2 ph = { (unsigned)h0 | ((unsigned)h1<<16), (unsigned)h2 | ((unsigned)h3<<16) };
                uint2 pl = { (unsigned)l0 | ((unsigned)l1<<16), (unsigned)l2 | ((unsigned)l3<<16) };
                *(uint2*)(rh + jj) = ph;
                *(uint2*)(rl + jj) = pl;
            }
        }
    }
    __syncthreads();

    // ---- Phase D: vec = P @ V^T ----
    load_tile64x32(sb + STRM_OFF*4, pvth, pvtl, 0, 512);
    cpcommit();
    float acc[2][2][4] = {};
    for (int kt = 0; kt < 16; ++kt) {
        if (kt < 15) {
            load_tile64x32(sb + (STRM_OFF + ((kt+1)&1)*VT_TILE_U32)*4, pvth, pvtl, (kt+1)*32, 512);
            cpcommit();
            cpwaitN<1>();
        } else cpwaitN<0>();
        __syncthreads();
        const uint32_t* TB = sm + STRM_OFF + (kt&1)*VT_TILE_U32;
        #pragma unroll
        for (int ks = 0; ks < 2; ++ks) {
            int g16 = kt*2 + ks;
            unsigned ah[2][4], al[2][4];
            #pragma unroll
            for (int mt = 0; mt < 2; ++mt) {
                int rb = wm + mt*16 + r;
                const uint32_t* RH0 = sm + rb*ARENA_ROW + g16*8;
                const uint32_t* RH1 = sm + (rb+8)*ARENA_ROW + g16*8;
                ah[mt][0] = RH0[c];        ah[mt][1] = RH1[c];
                ah[mt][2] = RH0[c + 4];    ah[mt][3] = RH1[c + 4];
                al[mt][0] = RH0[266 + c];     al[mt][1] = RH1[266 + c];
                al[mt][2] = RH0[266 + c + 4]; al[mt][3] = RH1[266 + c + 4];
            }
            #pragma unroll
            for (int nt = 0; nt < 2; ++nt) {
                int cb = wn + nt*8 + r;
                unsigned bh[2] = { TB[cb*20 + ks*8 + c], TB[cb*20 + ks*8 + c + 4] };
                unsigned bl[2] = { TB[1280 + cb*20 + ks*8 + c], TB[1280 + cb*20 + ks*8 + c + 4] };
                #pragma unroll
                for (int mt = 0; mt < 2; ++mt) {
                    mma16816(acc[mt][nt], ah[mt], bh);
                    mma16816(acc[mt][nt], ah[mt], bl);
                    mma16816(acc[mt][nt], al[mt], bh);
                }
            }
        }
        __syncthreads();
    }
    #pragma unroll
    for (int mt = 0; mt < 2; ++mt) {
        int i = i0 + wm + mt*16 + r;
        #pragma unroll
        for (int nt = 0; nt < 2; ++nt) {
            int d = wn + nt*8 + 2*c;
            size_t o0 = ((size_t)i * B_ + zb) * 512 + zn * 64 + d;
            size_t o1 = ((size_t)(i + 8) * B_ + zb) * 512 + zn * 64 + d;
            split2_store(vech, vecl, o0, acc[mt][nt][0], acc[mt][nt][1]);
            split2_store(vech, vecl, o1, acc[mt][nt][2], acc[mt][nt][3]);
        }
    }
}

// ------------------------- host orchestration -------------------------
template <typename Tp>
static Tp* symaddr(const void* sym)
{
    void* p = nullptr;
    cudaGetSymbolAddress(&p, sym);
    return (Tp*)p;
}

extern "C" void kernel_launch(void* const* d_in, const int* in_sizes, int n_in,
                              void* d_out, int out_size)
{
    const float* h_in  = (const float*)d_in[0];
    const void*  mraw  = d_in[1];
    const float* rwb   = (const float*)d_in[2];
    const float* rrb   = (const float*)d_in[3];
    const float* tlg   = (const float*)d_in[4];
    const float* tlb   = (const float*)d_in[5];
    const float* qkvw  = (const float*)d_in[6];
    const float* rnetw = (const float*)d_in[7];
    const float* ow    = (const float*)d_in[8];
    const float* alg   = (const float*)d_in[9];
    const float* alb   = (const float*)d_in[10];
    const float* w1    = (const float*)d_in[11];
    const float* b1    = (const float*)d_in[12];
    const float* w2    = (const float*)d_in[13];
    const float* b2    = (const float*)d_in[14];
    const float* flg   = (const float*)d_in[15];
    const float* flb   = (const float*)d_in[16];
    float* out = (float*)d_out;

    float* p_h    = symaddr<float>(g_h);
    bf16*  p_hh   = symaddr<bf16>(g_hh);
    bf16*  p_hl   = symaddr<bf16>(g_hl);
    bf16*  p_posh = symaddr<bf16>(g_posh);
    bf16*  p_posl = symaddr<bf16>(g_posl);
    bf16*  p_qw_h = symaddr<bf16>(g_qw_h); bf16* p_qw_l = symaddr<bf16>(g_qw_l);
    bf16*  p_qr_h = symaddr<bf16>(g_qr_h); bf16* p_qr_l = symaddr<bf16>(g_qr_l);
    bf16*  p_k_h  = symaddr<bf16>(g_k_h);  bf16* p_k_l  = symaddr<bf16>(g_k_l);
    bf16*  p_vth  = symaddr<bf16>(g_vth);  bf16* p_vtl  = symaddr<bf16>(g_vtl);
    bf16*  p_rkbf_h = symaddr<bf16>(g_rkbf_h); bf16* p_rkbf_l = symaddr<bf16>(g_rkbf_l);
    bf16*  p_vech = symaddr<bf16>(g_vech);
    bf16*  p_vecl = symaddr<bf16>(g_vecl);
    float* p_t1   = symaddr<float>(g_t1);
    bf16*  p_ffh  = symaddr<bf16>(g_ffh);
    bf16*  p_ffl  = symaddr<bf16>(g_ffl);
    unsigned char* p_pad = symaddr<unsigned char>(g_pad);

    bf16* p_qkvT_h = symaddr<bf16>(g_qkvT_h); bf16* p_qkvT_l = symaddr<bf16>(g_qkvT_l);
    bf16* p_rkT_h  = symaddr<bf16>(g_rkT_h);  bf16* p_rkT_l  = symaddr<bf16>(g_rkT_l);
    bf16* p_oT_h   = symaddr<bf16>(g_oT_h);   bf16* p_oT_l   = symaddr<bf16>(g_oT_l);
    bf16* p_w1T_h  = symaddr<bf16>(g_w1T_h);  bf16* p_w1T_l  = symaddr<bf16>(g_w1T_l);
    bf16* p_w2T_h  = symaddr<bf16>(g_w2T_h);  bf16* p_w2T_l  = symaddr<bf16>(g_w2T_l);

    auto k_qkv = gemm_v3<128,128,64,32,2>;
    auto k_rk  = gemm_v3<128,128,64,32,4>;
    auto k_f32 = gemm_v3<128,128,64,32,0>;
    auto k_ff1 = gemm_v3<128,128,64,32,1>;
    const int SMEM_BIG = (2*128*20 + 2*128*20) * 4 * 2;
    cudaFuncSetAttribute(k_qkv, cudaFuncAttributeMaxDynamicSharedMemorySize, SMEM_BIG);
    cudaFuncSetAttribute(k_rk,  cudaFuncAttributeMaxDynamicSharedMemorySize, SMEM_BIG);
    cudaFuncSetAttribute(k_f32, cudaFuncAttributeMaxDynamicSharedMemorySize, SMEM_BIG);
    cudaFuncSetAttribute(k_ff1, cudaFuncAttributeMaxDynamicSharedMemorySize, SMEM_BIG);
    cudaFuncSetAttribute(attn_fused, cudaFuncAttributeMaxDynamicSharedMemorySize, ATTN_SMEM_BYTES);

    const size_t BTD = (size_t)B_ * T_ * D_;

    wtrans_kernel<<<dim3(1536/32, 512/32, L_), 256>>>(qkvw, p_qkvT_h, p_qkvT_l, 512, 1536);
    wtrans_kernel<<<dim3(512/32, 512/32, L_), 256>>>(rnetw, p_rkT_h, p_rkT_l, 512, 512);
    wtrans_kernel<<<dim3(512/32, 512/32, L_), 256>>>(ow, p_oT_h, p_oT_l, 512, 512);
    wtrans_kernel<<<dim3(2048/32, 512/32, L_), 256>>>(w1, p_w1T_h, p_w1T_l, 512, 2048);
    wtrans_kernel<<<dim3(512/32, 2048/32, L_), 256>>>(w2, p_w2T_h, p_w2T_l, 2048, 512);

    mask_kernel<<<(B_*T_ + 255)/256, 256>>>((const unsigned char*)mraw, p_pad);
    pos_kernel<<<(2048*D_ + 255)/256, 256>>>(p_posh, p_posl);
    ln_kernel<<<T_*B_, 256>>>(h_in, nullptr, tlg, tlb, p_h, p_hh, p_hl, out + BTD, nullptr, 1);

    for (int i = 0; i < L_; ++i) {
        // QKV -> qw/qr/k/vT (split, per-head layouts)
        k_qkv<<<dim3(1536/128, (T_*B_)/128), 256, SMEM_BIG>>>(
            p_hh, p_hl, p_qkvT_h + (size_t)i*1536*512, p_qkvT_l + (size_t)i*1536*512,
            rwb, rrb, nullptr, nullptr, nullptr, T_*B_, 1536, 512);
        // rk -> split bf16 [2048][512]
        k_rk<<<dim3(512/128, 2048/128), 256, SMEM_BIG>>>(
            p_posh, p_posl, p_rkT_h + (size_t)i*512*512, p_rkT_l + (size_t)i*512*512,
            nullptr, nullptr, nullptr, p_rkbf_h, p_rkbf_l, 2048, 512, 512);
        // fused attention: AC + E(shift) + mask + softmax + AV
        attn_fused<<<dim3(T_/64, B_*H_), 256, ATTN_SMEM_BYTES>>>(
            p_qw_h, p_qw_l, p_qr_h, p_qr_l, p_k_h, p_k_l,
            p_rkbf_h, p_rkbf_l, p_vth, p_vtl, p_pad, p_vech, p_vecl);
        // O proj
        k_f32<<<dim3(512/128, (T_*B_)/128), 256, SMEM_BIG>>>(
            p_vech, p_vecl, p_oT_h + (size_t)i*512*512, p_oT_l + (size_t)i*512*512,
            nullptr, nullptr, p_t1, nullptr, nullptr, T_*B_, 512, 512);
        // out1 = LN(h + attn)
        ln_kernel<<<T_*B_, 256>>>(p_h, p_t1, alg + i*D_, alb + i*D_, p_h, p_hh, p_hl,
                                  nullptr, nullptr, 0);
        // FF1
        k_ff1<<<dim3(DI_/128, (T_*B_)/128), 256, SMEM_BIG>>>(
            p_hh, p_hl, p_w1T_h + (size_t)i*2048*512, p_w1T_l + (size_t)i*2048*512,
            b1 + (size_t)i*DI_, nullptr, nullptr, p_ffh, p_ffl, T_*B_, DI_, 512);
        // FF2
        k_f32<<<dim3(512/128, (T_*B_)/128), 256, SMEM_BIG>>>(
            p_ffh, p_ffl, p_w2T_h + (size_t)i*512*2048, p_w2T_l + (size_t)i*512*2048,
            b2 + (size_t)i*D_, nullptr, p_t1, nullptr, nullptr, T_*B_, 512, DI_);
        // layer out = LN(out1 + ff)
        float* hb0 = out + (size_t)(2 + i) * BTD;
        float* hb1 = (i == L_ - 1) ? out : nullptr;
        ln_kernel<<<T_*B_, 256>>>(p_h, p_t1, flg + i*D_, flb + i*D_, p_h, p_hh, p_hl,
                                  hb0, hb1, 0);
    }
}

// round 8
// speedup vs baseline: 2.5454x; 1.0281x over previous
#include <cuda_runtime.h>
#include <cuda_bf16.h>
#include <math.h>
#include <stdint.h>

#define T_  512
#define B_  16
#define D_  512
#define H_  8
#define DH_ 64
#define DI_ 2048
#define L_  4
#define SCALE_ (0.125f)
#define NEG_INF_ (-1e9f)

typedef __nv_bfloat16 bf16;

// ------------------------- static device scratch -------------------------
__device__ float g_h   [(size_t)T_*B_*D_];
__device__ bf16  g_hh  [(size_t)T_*B_*D_];
__device__ bf16  g_hl  [(size_t)T_*B_*D_];
__device__ bf16  g_posh[(size_t)2048*D_];
__device__ bf16  g_posl[(size_t)2048*D_];
// per-head attention operands, z = b*8 + n
__device__ bf16  g_qw_h[(size_t)128*512*64], g_qw_l[(size_t)128*512*64]; // pre-scaled
__device__ bf16  g_qr_h[(size_t)128*512*64], g_qr_l[(size_t)128*512*64];
__device__ bf16  g_k_h [(size_t)128*512*64], g_k_l [(size_t)128*512*64];
__device__ bf16  g_vth [(size_t)128*64*512], g_vtl [(size_t)128*64*512]; // [(z)*64+d][t]
__device__ bf16  g_rkbf_h[(size_t)(2048+64)*512], g_rkbf_l[(size_t)(2048+64)*512];
__device__ bf16  g_vech[(size_t)T_*B_*D_];
__device__ bf16  g_vecl[(size_t)T_*B_*D_];
__device__ float g_t1  [(size_t)T_*B_*D_];
__device__ bf16  g_ffh [(size_t)T_*B_*DI_];
__device__ bf16  g_ffl [(size_t)T_*B_*DI_];
__device__ unsigned char g_pad[B_*T_];
// transposed + split weights: [L][N][K]
__device__ bf16 g_qkvT_h[(size_t)L_*1536*512], g_qkvT_l[(size_t)L_*1536*512];
__device__ bf16 g_rkT_h [(size_t)L_*512*512],  g_rkT_l [(size_t)L_*512*512];
__device__ bf16 g_oT_h  [(size_t)L_*512*512],  g_oT_l  [(size_t)L_*512*512];
__device__ bf16 g_w1T_h [(size_t)L_*2048*512], g_w1T_l [(size_t)L_*2048*512];
__device__ bf16 g_w2T_h [(size_t)L_*512*2048], g_w2T_l [(size_t)L_*512*2048];

// ------------------------- helpers -------------------------
__device__ __forceinline__ void fsplit(float v, unsigned short& hi, unsigned short& lo)
{
    bf16 h = __float2bfloat16(v);
    float rem = v - __bfloat162float(h);
    bf16 l = __float2bfloat16(rem);
    hi = __bfloat16_as_ushort(h);
    lo = __bfloat16_as_ushort(l);
}

__device__ __forceinline__ void split2_store(bf16* oh, bf16* ol, size_t idx, float v0, float v1)
{
    unsigned short h0,l0,h1,l1;
    fsplit(v0,h0,l0); fsplit(v1,h1,l1);
    *(unsigned*)(oh + idx) = (unsigned)h0 | ((unsigned)h1 << 16);
    *(unsigned*)(ol + idx) = (unsigned)l0 | ((unsigned)l1 << 16);
}

__device__ __forceinline__ void mma16816(float* d, const unsigned* a, const unsigned* b)
{
    asm volatile(
        "mma.sync.aligned.m16n8k16.row.col.f32.bf16.bf16.f32 "
        "{%0,%1,%2,%3},{%4,%5,%6,%7},{%8,%9},{%0,%1,%2,%3};"
        : "+f"(d[0]), "+f"(d[1]), "+f"(d[2]), "+f"(d[3])
        : "r"(a[0]), "r"(a[1]), "r"(a[2]), "r"(a[3]), "r"(b[0]), "r"(b[1]));
}

__device__ __forceinline__ void ldsm4(unsigned* d, uint32_t a)
{
    asm volatile("ldmatrix.sync.aligned.m8n8.x4.shared.b16 {%0,%1,%2,%3}, [%4];"
        : "=r"(d[0]), "=r"(d[1]), "=r"(d[2]), "=r"(d[3]) : "r"(a));
}

__device__ __forceinline__ void ldsm2(unsigned* d, uint32_t a)
{
    asm volatile("ldmatrix.sync.aligned.m8n8.x2.shared.b16 {%0,%1}, [%2];"
        : "=r"(d[0]), "=r"(d[1]) : "r"(a));
}

__device__ __forceinline__ void cpasync16(uint32_t saddr, const void* gptr)
{
    asm volatile("cp.async.cg.shared.global [%0], [%1], 16;" :: "r"(saddr), "l"(gptr));
}
__device__ __forceinline__ void cpcommit() { asm volatile("cp.async.commit_group;"); }
template<int N> __device__ __forceinline__ void cpwaitN()
{ asm volatile("cp.async.wait_group %0;" :: "n"(N)); }

// ------------------------- weight transpose + split -------------------------
__global__ __launch_bounds__(256)
void wtrans_kernel(const float* __restrict__ W, bf16* __restrict__ oh, bf16* __restrict__ ol,
                   int K, int N)
{
    __shared__ float t[32][33];
    int z = blockIdx.z;
    const float* Wz = W + (size_t)z * K * N;
    bf16* ohz = oh + (size_t)z * N * K;
    bf16* olz = ol + (size_t)z * N * K;
    int n0 = blockIdx.x * 32, k0 = blockIdx.y * 32;
    int tx = threadIdx.x & 31, ty = threadIdx.x >> 5;
    #pragma unroll
    for (int i = 0; i < 4; ++i)
        t[ty + 8*i][tx] = Wz[(size_t)(k0 + ty + 8*i) * N + n0 + tx];
    __syncthreads();
    #pragma unroll
    for (int i = 0; i < 4; ++i) {
        int n = n0 + ty + 8*i, k = k0 + tx;
        unsigned short h, l;
        fsplit(t[tx][ty + 8*i], h, l);
        ohz[(size_t)n * K + k] = __ushort_as_bfloat16(h);
        olz[(size_t)n * K + k] = __ushort_as_bfloat16(l);
    }
}

// ------------------------- mask build (dtype-robust) -------------------------
__global__ void mask_kernel(const unsigned char* __restrict__ raw, unsigned char* __restrict__ pad)
{
    int idx = blockIdx.x * blockDim.x + threadIdx.x;
    if (idx >= B_ * T_) return;
    unsigned char b0 = raw[0], b1 = raw[1];
    bool m;
    if (b0 == 1 && b1 == 1)      m = raw[idx] != 0;
    else if (b0 == 1)            m = ((const int*)raw)[idx] != 0;
    else                         m = ((const float*)raw)[idx] != 0.0f;
    pad[idx] = m ? 0 : 1;
}

// ------------------------- positional embeddings (split bf16) -------------------------
__global__ void pos_kernel(bf16* __restrict__ ph, bf16* __restrict__ pl)
{
    int idx = blockIdx.x * blockDim.x + threadIdx.x;
    if (idx >= 2048 * D_) return;
    int m = idx / D_;
    int k = idx - m * D_;
    int grp = m >> 10;
    int mm  = m & 1023;
    float p = (grp == 0) ? (float)(T_ - mm) : (float)(mm - T_);
    int kk = (k < 256) ? k : (k - 256);
    float invf = powf(10000.0f, -((float)(2 * kk) / (float)D_));
    float s = p * invf;
    float v = (k < 256) ? sinf(s) : cosf(s);
    unsigned short h, l;
    fsplit(v, h, l);
    ph[idx] = __ushort_as_bfloat16(h);
    pl[idx] = __ushort_as_bfloat16(l);
}

// ------------------------- layernorm -------------------------
__global__ __launch_bounds__(256)
void ln_kernel(const float* __restrict__ x, const float* __restrict__ addv,
               const float* __restrict__ g, const float* __restrict__ be,
               float* __restrict__ out_seq, bf16* __restrict__ outh, bf16* __restrict__ outl,
               float* __restrict__ outb0, float* __restrict__ outb1, int in_bt)
{
    int row = blockIdx.x;
    int t = row / B_, b = row - t * B_;
    size_t iseq = (size_t)row * D_;
    size_t ibt  = ((size_t)b * T_ + t) * D_;
    const float* px = x + (in_bt ? ibt : iseq);
    int d0 = threadIdx.x, d1 = threadIdx.x + 256;
    float v0 = px[d0], v1 = px[d1];
    if (addv) { v0 += addv[iseq + d0]; v1 += addv[iseq + d1]; }
    float s = v0 + v1;
    float q = v0 * v0 + v1 * v1;
    __shared__ float sh[2][8];
    #pragma unroll
    for (int o = 16; o; o >>= 1) {
        s += __shfl_xor_sync(0xffffffffu, s, o);
        q += __shfl_xor_sync(0xffffffffu, q, o);
    }
    int w = threadIdx.x >> 5, ln = threadIdx.x & 31;
    if (ln == 0) { sh[0][w] = s; sh[1][w] = q; }
    __syncthreads();
    if (threadIdx.x < 32) {
        s = (ln < 8) ? sh[0][ln] : 0.f;
        q = (ln < 8) ? sh[1][ln] : 0.f;
        #pragma unroll
        for (int o = 4; o; o >>= 1) {
            s += __shfl_xor_sync(0xffffffffu, s, o);
            q += __shfl_xor_sync(0xffffffffu, q, o);
        }
        if (ln == 0) { sh[0][0] = s; sh[1][0] = q; }
    }
    __syncthreads();
    float mean = sh[0][0] * (1.0f / 512.0f);
    float var  = sh[1][0] * (1.0f / 512.0f) - mean * mean;
    float r = rsqrtf(var + 1e-6f);
    float y0 = (v0 - mean) * r * g[d0] + be[d0];
    float y1 = (v1 - mean) * r * g[d1] + be[d1];
    out_seq[iseq + d0] = y0; out_seq[iseq + d1] = y1;
    unsigned short h0, l0, h1, l1;
    fsplit(y0, h0, l0); fsplit(y1, h1, l1);
    outh[iseq + d0] = __ushort_as_bfloat16(h0); outh[iseq + d1] = __ushort_as_bfloat16(h1);
    outl[iseq + d0] = __ushort_as_bfloat16(l0); outl[iseq + d1] = __ushort_as_bfloat16(l1);
    if (outb0) { outb0[ibt + d0] = y0; outb0[ibt + d1] = y1; }
    if (outb1) { outb1[ibt + d0] = y0; outb1[ibt + d1] = y1; }
}

// ------------------------- GEMM v3 (dense layers), LDSM fragments -------------------------
// MODE 0: Cf fp32 (+bias);  MODE 1: bias+relu+split;  MODE 2: QKV epilogue;  MODE 4: split row-major
template<int BM, int BN, int WM, int WN, int MODE>
__global__ void __launch_bounds__(256)
gemm_v3(const bf16* __restrict__ Ah, const bf16* __restrict__ Al,
        const bf16* __restrict__ Bh, const bf16* __restrict__ Bl,
        const float* __restrict__ bias, const float* __restrict__ bias2,
        float* __restrict__ Cf, bf16* __restrict__ Oh, bf16* __restrict__ Ol,
        int M, int N, int K)
{
    constexpr int MT = WM / 16, NT = WN / 8;
    constexpr int NWM = BM / WM;
    constexpr int NA = BM * 4, NB = BN * 4, TOTAL = 2 * (NA + NB);
    constexpr int SA = BM * 20, SB = BN * 20;
    constexpr int S = 2 * SA + 2 * SB;

    extern __shared__ uint32_t smem[];
    uint32_t sbase = (uint32_t)__cvta_generic_to_shared(smem);

    int m0 = blockIdx.y * BM, n0 = blockIdx.x * BN;
    int tid = threadIdx.x, lane = tid & 31, w = tid >> 5;
    int wm = (w % NWM) * WM, wn = (w / NWM) * WN;
    int r = lane >> 2, c = lane & 3;

    float acc[MT][NT][4];
    #pragma unroll
    for (int i = 0; i < MT; ++i)
        #pragma unroll
        for (int j = 0; j < NT; ++j)
            #pragma unroll
            for (int q = 0; q < 4; ++q) acc[i][j][q] = 0.f;

    auto prefetch = [&](int kt, int st) {
        uint32_t base = sbase + (uint32_t)st * S * 4;
        #pragma unroll
        for (int l = 0; l < TOTAL / 256; ++l) {
            int q = tid + l * 256;
            const bf16* gp; uint32_t off;
            if (q < NA) {
                int row = q >> 2, seg = q & 3;
                gp = Ah + (size_t)(m0 + row) * K + kt + seg * 8;
                off = row * 20 + seg * 4;
            } else if (q < 2 * NA) {
                int p = q - NA; int row = p >> 2, seg = p & 3;
                gp = Al + (size_t)(m0 + row) * K + kt + seg * 8;
                off = SA + row * 20 + seg * 4;
            } else if (q < 2 * NA + NB) {
                int p = q - 2 * NA; int row = p >> 2, seg = p & 3;
                gp = Bh + (size_t)(n0 + row) * K + kt + seg * 8;
                off = 2 * SA + row * 20 + seg * 4;
            } else {
                int p = q - 2 * NA - NB; int row = p >> 2, seg = p & 3;
                gp = Bl + (size_t)(n0 + row) * K + kt + seg * 8;
                off = 2 * SA + SB + row * 20 + seg * 4;
            }
            cpasync16(base + off * 4, gp);
        }
        cpcommit();
    };

    uint32_t aRowOff = (lane & 7) + ((lane >> 3) & 1) * 8;
    uint32_t aChunk  = (lane >> 4) * 16;
    uint32_t bRowOff = lane & 7;
    uint32_t bChunk  = ((lane >> 3) & 1) * 16;

    auto compute = [&](int st) {
        uint32_t stb = sbase + (uint32_t)st * S * 4;
        #pragma unroll
        for (int ks = 0; ks < 2; ++ks) {
            unsigned ah[MT][4], al[MT][4];
            #pragma unroll
            for (int mt = 0; mt < MT; ++mt) {
                uint32_t ab = stb + (uint32_t)(wm + mt * 16 + aRowOff) * 80 + ks * 32 + aChunk;
                ldsm4(ah[mt], ab);
                ldsm4(al[mt], ab + SA * 4);
            }
            #pragma unroll
            for (int nt = 0; nt < NT; ++nt) {
                uint32_t bb = stb + 2u * SA * 4 + (uint32_t)(wn + nt * 8 + bRowOff) * 80
                              + ks * 32 + bChunk;
                unsigned bh[2], bl[2];
                ldsm2(bh, bb);
                ldsm2(bl, bb + SB * 4);
                #pragma unroll
                for (int mt = 0; mt < MT; ++mt) {
                    mma16816(acc[mt][nt], ah[mt], bh);
                    mma16816(acc[mt][nt], ah[mt], bl);
                    mma16816(acc[mt][nt], al[mt], bh);
                }
            }
        }
    };

    int nk = K / 32;
    prefetch(0, 0);
    for (int i = 0; i < nk; ++i) {
        cpwaitN<0>();
        __syncthreads();
        if (i + 1 < nk) prefetch((i + 1) * 32, (i + 1) & 1);
        compute(i & 1);
    }

    #pragma unroll
    for (int mt = 0; mt < MT; ++mt) {
        int row = m0 + wm + mt * 16 + r;
        #pragma unroll
        for (int nt = 0; nt < NT; ++nt) {
            int col = n0 + wn + nt * 8 + 2 * c;
            float v0 = acc[mt][nt][0], v1 = acc[mt][nt][1];
            float v2 = acc[mt][nt][2], v3 = acc[mt][nt][3];
            if (MODE == 0) {
                if (bias) { v0 += bias[col]; v1 += bias[col+1]; v2 += bias[col]; v3 += bias[col+1]; }
                float2 w0 = {v0, v1}, w1 = {v2, v3};
                *(float2*)(Cf + (size_t)row * N + col) = w0;
                *(float2*)(Cf + (size_t)(row + 8) * N + col) = w1;
            } else if (MODE == 1) {
                float bb0 = bias[col], bb1 = bias[col+1];
                v0 = fmaxf(v0 + bb0, 0.f); v1 = fmaxf(v1 + bb1, 0.f);
                v2 = fmaxf(v2 + bb0, 0.f); v3 = fmaxf(v3 + bb1, 0.f);
                split2_store(Oh, Ol, (size_t)row * N + col, v0, v1);
                split2_store(Oh, Ol, (size_t)(row + 8) * N + col, v2, v3);
            } else if (MODE == 2) {
                if (col < 512) {
                    int hn = col >> 6, d = col & 63;
                    float rw0 = bias[col], rw1 = bias[col+1];
                    float rr0 = bias2[col], rr1 = bias2[col+1];
                    {
                        int bb = row & 15, tt = row >> 4;
                        size_t base = ((size_t)(bb*8+hn)*512 + tt)*64 + d;
                        split2_store(g_qw_h, g_qw_l, base, (v0+rw0)*SCALE_, (v1+rw1)*SCALE_);
                        split2_store(g_qr_h, g_qr_l, base, (v0+rr0)*SCALE_, (v1+rr1)*SCALE_);
                    }
                    {
                        int r2 = row + 8;
                        int bb = r2 & 15, tt = r2 >> 4;
                        size_t base = ((size_t)(bb*8+hn)*512 + tt)*64 + d;
                        split2_store(g_qw_h, g_qw_l, base, (v2+rw0)*SCALE_, (v3+rw1)*SCALE_);
                        split2_store(g_qr_h, g_qr_l, base, (v2+rr0)*SCALE_, (v3+rr1)*SCALE_);
                    }
                } else if (col < 1024) {
                    int cc = col - 512;
                    int hn = cc >> 6, d = cc & 63;
                    {
                        int bb = row & 15, tt = row >> 4;
                        size_t base = ((size_t)(bb*8+hn)*512 + tt)*64 + d;
                        split2_store(g_k_h, g_k_l, base, v0, v1);
                    }
                    {
                        int r2 = row + 8;
                        int bb = r2 & 15, tt = r2 >> 4;
                        size_t base = ((size_t)(bb*8+hn)*512 + tt)*64 + d;
                        split2_store(g_k_h, g_k_l, base, v2, v3);
                    }
                } else {
                    int dp = col - 1024;
                    int hn = dp >> 6, d = dp & 63;
                    {
                        int bb = row & 15, tt = row >> 4;
                        size_t base = ((size_t)(bb*8+hn)*64 + d)*512 + tt;
                        unsigned short h, l;
                        fsplit(v0, h, l); g_vth[base] = __ushort_as_bfloat16(h); g_vtl[base] = __ushort_as_bfloat16(l);
                        fsplit(v1, h, l); g_vth[base + 512] = __ushort_as_bfloat16(h); g_vtl[base + 512] = __ushort_as_bfloat16(l);
                    }
                    {
                        int r2 = row + 8;
                        int bb = r2 & 15, tt = r2 >> 4;
                        size_t base = ((size_t)(bb*8+hn)*64 + d)*512 + tt;
                        unsigned short h, l;
                        fsplit(v2, h, l); g_vth[base] = __ushort_as_bfloat16(h); g_vtl[base] = __ushort_as_bfloat16(l);
                        fsplit(v3, h, l); g_vth[base + 512] = __ushort_as_bfloat16(h); g_vtl[base + 512] = __ushort_as_bfloat16(l);
                    }
                }
            } else { // MODE 4
                split2_store(Oh, Ol, (size_t)row * N + col, v0, v1);
                split2_store(Oh, Ol, (size_t)(row + 8) * N + col, v2, v3);
            }
        }
    }
}

// ------------------------- fused attention -------------------------
#define ARENA_ROW 532
#define ARENA_U32 (64*ARENA_ROW)
#define STRM_OFF  ARENA_U32
#define TILE_U32  5120
#define VT_TILE_U32 2560
#define QBUF_OFF  (STRM_OFF + 2*TILE_U32)
#define ATTN_SMEM_U32 (QBUF_OFF + TILE_U32)
#define ATTN_SMEM_BYTES (ATTN_SMEM_U32*4)
#define P_LO_OFF 272    // u32 offset of lo plane within arena row (1088 B, 16B-aligned)

__device__ __forceinline__ void load_tile64x64(uint32_t sb, const bf16* gh, const bf16* gl,
                                               int r0, int ld)
{
    int tid = threadIdx.x;
    #pragma unroll
    for (int l = 0; l < 4; ++l) {
        int q = tid + l*256;
        int comp = q >> 9, p = q & 511;
        int row = p >> 3, seg = p & 7;
        int kc = seg >> 2, u = (seg & 3) * 4;
        const bf16* g = (comp ? gl : gh) + (size_t)(r0 + row) * ld + seg * 8;
        uint32_t off = (uint32_t)(comp * 2560 + kc * 1280 + row * 20 + u);
        cpasync16(sb + off * 4, g);
    }
}

__device__ __forceinline__ void load_tile64x32(uint32_t sb, const bf16* gh, const bf16* gl,
                                               int c0, int ld)
{
    int tid = threadIdx.x;
    #pragma unroll
    for (int l = 0; l < 2; ++l) {
        int q = tid + l*256;
        int comp = q >> 8, p = q & 255;
        int row = p >> 2, seg = p & 3;
        const bf16* g = (comp ? gl : gh) + (size_t)row * ld + c0 + seg * 8;
        uint32_t off = (uint32_t)(comp * 1280 + row * 20 + seg * 4);
        cpasync16(sb + off * 4, g);
    }
}

// 32x16 warp tile over one 64-col tile; K=64 (2 chunks), LDSM fragments
__device__ __forceinline__ void mma_qt(float acc[2][2][4], uint32_t sbase,
                                       int qoff, int toff, int wm, int wn, int lane)
{
    uint32_t aRowOff = (lane & 7) + ((lane >> 3) & 1) * 8;
    uint32_t aChunk  = (lane >> 4) * 16;
    uint32_t bRowOff = lane & 7;
    uint32_t bChunk  = ((lane >> 3) & 1) * 16;
    #pragma unroll
    for (int kc = 0; kc < 2; ++kc) {
        uint32_t qb = sbase + (uint32_t)(qoff + kc*1280) * 4;
        uint32_t tb = sbase + (uint32_t)(toff + kc*1280) * 4;
        #pragma unroll
        for (int ks = 0; ks < 2; ++ks) {
            unsigned ah[2][4], al[2][4];
            #pragma unroll
            for (int mt = 0; mt < 2; ++mt) {
                uint32_t ab = qb + (uint32_t)(wm + mt*16 + aRowOff) * 80 + ks*32 + aChunk;
                ldsm4(ah[mt], ab);
                ldsm4(al[mt], ab + 2560*4);
            }
            #pragma unroll
            for (int nt = 0; nt < 2; ++nt) {
                uint32_t bb = tb + (uint32_t)(wn + nt*8 + bRowOff) * 80 + ks*32 + bChunk;
                unsigned bh[2], bl[2];
                ldsm2(bh, bb);
                ldsm2(bl, bb + 2560*4);
                #pragma unroll
                for (int mt = 0; mt < 2; ++mt) {
                    mma16816(acc[mt][nt], ah[mt], bh);
                    mma16816(acc[mt][nt], ah[mt], bl);
                    mma16816(acc[mt][nt], al[mt], bh);
                }
            }
        }
    }
}

__global__ __launch_bounds__(256)
void attn_fused(const bf16* __restrict__ qwh, const bf16* __restrict__ qwl,
                const bf16* __restrict__ qrh, const bf16* __restrict__ qrl,
                const bf16* __restrict__ kh,  const bf16* __restrict__ kl,
                const bf16* __restrict__ rkh, const bf16* __restrict__ rkl,
                const bf16* __restrict__ vth, const bf16* __restrict__ vtl,
                const unsigned char* __restrict__ pad,
                bf16* __restrict__ vech, bf16* __restrict__ vecl)
{
    extern __shared__ uint32_t sm[];
    float* Sf = (float*)sm;
    uint32_t sb = (uint32_t)__cvta_generic_to_shared(sm);

    int i0 = blockIdx.x * 64;
    int z = blockIdx.y;
    int zb = z >> 3, zn = z & 7;
    int grp = (zb >= 8) ? 1 : 0;
    int tid = threadIdx.x, lane = tid & 31, w = tid >> 5;
    int wm = (w & 1) * 32, wn = (w >> 1) * 16;
    int r = lane >> 2, c = lane & 3;

    const size_t zoff = (size_t)z * 512 * 64;
    const bf16* pqwh = qwh + zoff; const bf16* pqwl = qwl + zoff;
    const bf16* pqrh = qrh + zoff; const bf16* pqrl = qrl + zoff;
    const bf16* pkh  = kh  + zoff; const bf16* pkl  = kl  + zoff;
    const bf16* pvth = vth + zoff; const bf16* pvtl = vtl + zoff;
    int m_lo = 449 - i0;
    const bf16* prkh = rkh + ((size_t)(grp*1024 + m_lo)) * 512 + zn * 64;
    const bf16* prkl = rkl + ((size_t)(grp*1024 + m_lo)) * 512 + zn * 64;

    // ---- Phase A: S = qw @ k^T ----
    load_tile64x64(sb + QBUF_OFF*4, pqwh, pqwl, i0, 64);
    load_tile64x64(sb + STRM_OFF*4, pkh, pkl, 0, 64);
    cpcommit();
    for (int jt = 0; jt < 8; ++jt) {
        if (jt < 7) {
            load_tile64x64(sb + (STRM_OFF + ((jt+1)&1)*TILE_U32)*4, pkh, pkl, (jt+1)*64, 64);
            cpcommit();
            cpwaitN<1>();
        } else cpwaitN<0>();
        __syncthreads();
        float acc[2][2][4] = {};
        mma_qt(acc, sb, QBUF_OFF, STRM_OFF + (jt&1)*TILE_U32, wm, wn, lane);
        #pragma unroll
        for (int mt = 0; mt < 2; ++mt) {
            int il = wm + mt*16 + r;
            #pragma unroll
            for (int nt = 0; nt < 2; ++nt) {
                int j = jt*64 + wn + nt*8 + 2*c;
                *(float2*)(Sf + il*ARENA_ROW + j)     = make_float2(acc[mt][nt][0], acc[mt][nt][1]);
                *(float2*)(Sf + (il+8)*ARENA_ROW + j) = make_float2(acc[mt][nt][2], acc[mt][nt][3]);
            }
        }
        __syncthreads();
    }

    // ---- Phase B: E = qr @ rk_band^T, scatter-add into S ----
    load_tile64x64(sb + QBUF_OFF*4, pqrh, pqrl, i0, 64);
    load_tile64x64(sb + STRM_OFF*4, prkh, prkl, 0, 512);
    cpcommit();
    for (int mt9 = 0; mt9 < 9; ++mt9) {
        if (mt9 < 8) {
            load_tile64x64(sb + (STRM_OFF + ((mt9+1)&1)*TILE_U32)*4, prkh, prkl, (mt9+1)*64, 512);
            cpcommit();
            cpwaitN<1>();
        } else cpwaitN<0>();
        __syncthreads();
        float acc[2][2][4] = {};
        mma_qt(acc, sb, QBUF_OFF, STRM_OFF + (mt9&1)*TILE_U32, wm, wn, lane);
        #pragma unroll
        for (int mt = 0; mt < 2; ++mt) {
            #pragma unroll
            for (int nt = 0; nt < 2; ++nt) {
                int mloc = mt9*64 + wn + nt*8 + 2*c;
                int il = wm + mt*16 + r;
                int j = mloc + il - 63;
                if (j >= 0   && j < 512)   Sf[il*ARENA_ROW + j]       += acc[mt][nt][0];
                if (j+1 >= 0 && j+1 < 512) Sf[il*ARENA_ROW + j + 1]   += acc[mt][nt][1];
                int il2 = il + 8;
                int j2 = mloc + il2 - 63;
                if (j2 >= 0   && j2 < 512)   Sf[il2*ARENA_ROW + j2]     += acc[mt][nt][2];
                if (j2+1 >= 0 && j2+1 < 512) Sf[il2*ARENA_ROW + j2 + 1] += acc[mt][nt][3];
            }
        }
        __syncthreads();
    }

    // ---- Phase C: mask + softmax + in-place split-P ----
    {
        const unsigned char* pb = pad + zb * T_;
        for (int rr = 0; rr < 8; ++rr) {
            int il = w*8 + rr;
            float* row = Sf + il*ARENA_ROW;
            float vv[16];
            #pragma unroll
            for (int q4 = 0; q4 < 4; ++q4) {
                int jb = (lane + 32*q4) * 4;
                float4 t = *(float4*)(row + jb);
                unsigned pm = *(const unsigned*)(pb + jb);
                vv[q4*4+0] = (pm & 0xffu)        ? NEG_INF_ : t.x;
                vv[q4*4+1] = (pm & 0xff00u)      ? NEG_INF_ : t.y;
                vv[q4*4+2] = (pm & 0xff0000u)    ? NEG_INF_ : t.z;
                vv[q4*4+3] = (pm & 0xff000000u)  ? NEG_INF_ : t.w;
            }
            float mx = vv[0];
            #pragma unroll
            for (int i = 1; i < 16; ++i) mx = fmaxf(mx, vv[i]);
            #pragma unroll
            for (int o = 16; o; o >>= 1) mx = fmaxf(mx, __shfl_xor_sync(0xffffffffu, mx, o));
            float s = 0.f;
            #pragma unroll
            for (int i = 0; i < 16; ++i) { vv[i] = expf(vv[i] - mx); s += vv[i]; }
            #pragma unroll
            for (int o = 16; o; o >>= 1) s += __shfl_xor_sync(0xffffffffu, s, o);
            float inv = 1.0f / s;
            uint32_t* rh = sm + il*ARENA_ROW;
            uint32_t* rl = rh + P_LO_OFF;
            #pragma unroll
            for (int q4 = 0; q4 < 4; ++q4) {
                int jj = (lane + 32*q4) * 2;
                unsigned short h0,l0,h1,l1,h2,l2,h3,l3;
                fsplit(vv[q4*4+0]*inv, h0, l0);
                fsplit(vv[q4*4+1]*inv, h1, l1);
                fsplit(vv[q4*4+2]*inv, h2, l2);
                fsplit(vv[q4*4+3]*inv, h3, l3);
                uint2 ph = { (unsigned)h0 | ((unsigned)h1<<16), (unsigned)h2 | ((unsigned)h3<<16) };
                uint2 pl = { (unsigned)l0 | ((unsigned)l1<<16), (unsigned)l2 | ((unsigned)l3<<16) };
                *(uint2*)(rh + jj) = ph;
                *(uint2*)(rl + jj) = pl;
            }
        }
    }
    __syncthreads();

    // ---- Phase D: vec = P @ V^T (LDSM fragments) ----
    uint32_t aRowOff = (lane & 7) + ((lane >> 3) & 1) * 8;
    uint32_t aChunk  = (lane >> 4) * 16;
    uint32_t bRowOff = lane & 7;
    uint32_t bChunk  = ((lane >> 3) & 1) * 16;
    load_tile64x32(sb + STRM_OFF*4, pvth, pvtl, 0, 512);
    cpcommit();
    float acc[2][2][4] = {};
    for (int kt = 0; kt < 16; ++kt) {
        if (kt < 15) {
            load_tile64x32(sb + (STRM_OFF + ((kt+1)&1)*VT_TILE_U32)*4, pvth, pvtl, (kt+1)*32, 512);
            cpcommit();
            cpwaitN<1>();
        } else cpwaitN<0>();
        __syncthreads();
        uint32_t tbb = sb + (uint32_t)(STRM_OFF + (kt&1)*VT_TILE_U32) * 4;
        #pragma unroll
        for (int ks = 0; ks < 2; ++ks) {
            int g16 = kt*2 + ks;
            unsigned ah[2][4], al[2][4];
            #pragma unroll
            for (int mt = 0; mt < 2; ++mt) {
                uint32_t ab = sb + (uint32_t)(wm + mt*16 + aRowOff) * (ARENA_ROW*4)
                              + (uint32_t)g16 * 32 + aChunk;
                ldsm4(ah[mt], ab);
                ldsm4(al[mt], ab + P_LO_OFF*4);
            }
            #pragma unroll
            for (int nt = 0; nt < 2; ++nt) {
                uint32_t bb = tbb + (uint32_t)(wn + nt*8 + bRowOff) * 80 + ks*32 + bChunk;
                unsigned bh[2], bl[2];
                ldsm2(bh, bb);
                ldsm2(bl, bb + 1280*4);
                #pragma unroll
                for (int mt = 0; mt < 2; ++mt) {
                    mma16816(acc[mt][nt], ah[mt], bh);
                    mma16816(acc[mt][nt], ah[mt], bl);
                    mma16816(acc[mt][nt], al[mt], bh);
                }
            }
        }
        __syncthreads();
    }
    #pragma unroll
    for (int mt = 0; mt < 2; ++mt) {
        int i = i0 + wm + mt*16 + r;
        #pragma unroll
        for (int nt = 0; nt < 2; ++nt) {
            int d = wn + nt*8 + 2*c;
            size_t o0 = ((size_t)i * B_ + zb) * 512 + zn * 64 + d;
            size_t o1 = ((size_t)(i + 8) * B_ + zb) * 512 + zn * 64 + d;
            split2_store(vech, vecl, o0, acc[mt][nt][0], acc[mt][nt][1]);
            split2_store(vech, vecl, o1, acc[mt][nt][2], acc[mt][nt][3]);
        }
    }
}

// ------------------------- host orchestration -------------------------
template <typename Tp>
static Tp* symaddr(const void* sym)
{
    void* p = nullptr;
    cudaGetSymbolAddress(&p, sym);
    return (Tp*)p;
}

extern "C" void kernel_launch(void* const* d_in, const int* in_sizes, int n_in,
                              void* d_out, int out_size)
{
    const float* h_in  = (const float*)d_in[0];
    const void*  mraw  = d_in[1];
    const float* rwb   = (const float*)d_in[2];
    const float* rrb   = (const float*)d_in[3];
    const float* tlg   = (const float*)d_in[4];
    const float* tlb   = (const float*)d_in[5];
    const float* qkvw  = (const float*)d_in[6];
    const float* rnetw = (const float*)d_in[7];
    const float* ow    = (const float*)d_in[8];
    const float* alg   = (const float*)d_in[9];
    const float* alb   = (const float*)d_in[10];
    const float* w1    = (const float*)d_in[11];
    const float* b1    = (const float*)d_in[12];
    const float* w2    = (const float*)d_in[13];
    const float* b2    = (const float*)d_in[14];
    const float* flg   = (const float*)d_in[15];
    const float* flb   = (const float*)d_in[16];
    float* out = (float*)d_out;

    float* p_h    = symaddr<float>(g_h);
    bf16*  p_hh   = symaddr<bf16>(g_hh);
    bf16*  p_hl   = symaddr<bf16>(g_hl);
    bf16*  p_posh = symaddr<bf16>(g_posh);
    bf16*  p_posl = symaddr<bf16>(g_posl);
    bf16*  p_qw_h = symaddr<bf16>(g_qw_h); bf16* p_qw_l = symaddr<bf16>(g_qw_l);
    bf16*  p_qr_h = symaddr<bf16>(g_qr_h); bf16* p_qr_l = symaddr<bf16>(g_qr_l);
    bf16*  p_k_h  = symaddr<bf16>(g_k_h);  bf16* p_k_l  = symaddr<bf16>(g_k_l);
    bf16*  p_vth  = symaddr<bf16>(g_vth);  bf16* p_vtl  = symaddr<bf16>(g_vtl);
    bf16*  p_rkbf_h = symaddr<bf16>(g_rkbf_h); bf16* p_rkbf_l = symaddr<bf16>(g_rkbf_l);
    bf16*  p_vech = symaddr<bf16>(g_vech);
    bf16*  p_vecl = symaddr<bf16>(g_vecl);
    float* p_t1   = symaddr<float>(g_t1);
    bf16*  p_ffh  = symaddr<bf16>(g_ffh);
    bf16*  p_ffl  = symaddr<bf16>(g_ffl);
    unsigned char* p_pad = symaddr<unsigned char>(g_pad);

    bf16* p_qkvT_h = symaddr<bf16>(g_qkvT_h); bf16* p_qkvT_l = symaddr<bf16>(g_qkvT_l);
    bf16* p_rkT_h  = symaddr<bf16>(g_rkT_h);  bf16* p_rkT_l  = symaddr<bf16>(g_rkT_l);
    bf16* p_oT_h   = symaddr<bf16>(g_oT_h);   bf16* p_oT_l   = symaddr<bf16>(g_oT_l);
    bf16* p_w1T_h  = symaddr<bf16>(g_w1T_h);  bf16* p_w1T_l  = symaddr<bf16>(g_w1T_l);
    bf16* p_w2T_h  = symaddr<bf16>(g_w2T_h);  bf16* p_w2T_l  = symaddr<bf16>(g_w2T_l);

    auto k_qkv = gemm_v3<128,128,64,32,2>;
    auto k_rk  = gemm_v3<128,128,64,32,4>;
    auto k_f32 = gemm_v3<128,128,64,32,0>;
    auto k_ff1 = gemm_v3<128,128,64,32,1>;
    const int SMEM_BIG = (2*128*20 + 2*128*20) * 4 * 2;
    cudaFuncSetAttribute(k_qkv, cudaFuncAttributeMaxDynamicSharedMemorySize, SMEM_BIG);
    cudaFuncSetAttribute(k_rk,  cudaFuncAttributeMaxDynamicSharedMemorySize, SMEM_BIG);
    cudaFuncSetAttribute(k_f32, cudaFuncAttributeMaxDynamicSharedMemorySize, SMEM_BIG);
    cudaFuncSetAttribute(k_ff1, cudaFuncAttributeMaxDynamicSharedMemorySize, SMEM_BIG);
    cudaFuncSetAttribute(attn_fused, cudaFuncAttributeMaxDynamicSharedMemorySize, ATTN_SMEM_BYTES);

    const size_t BTD = (size_t)B_ * T_ * D_;

    wtrans_kernel<<<dim3(1536/32, 512/32, L_), 256>>>(qkvw, p_qkvT_h, p_qkvT_l, 512, 1536);
    wtrans_kernel<<<dim3(512/32, 512/32, L_), 256>>>(rnetw, p_rkT_h, p_rkT_l, 512, 512);
    wtrans_kernel<<<dim3(512/32, 512/32, L_), 256>>>(ow, p_oT_h, p_oT_l, 512, 512);
    wtrans_kernel<<<dim3(2048/32, 512/32, L_), 256>>>(w1, p_w1T_h, p_w1T_l, 512, 2048);
    wtrans_kernel<<<dim3(512/32, 2048/32, L_), 256>>>(w2, p_w2T_h, p_w2T_l, 2048, 512);

    mask_kernel<<<(B_*T_ + 255)/256, 256>>>((const unsigned char*)mraw, p_pad);
    pos_kernel<<<(2048*D_ + 255)/256, 256>>>(p_posh, p_posl);
    ln_kernel<<<T_*B_, 256>>>(h_in, nullptr, tlg, tlb, p_h, p_hh, p_hl, out + BTD, nullptr, 1);

    for (int i = 0; i < L_; ++i) {
        // QKV -> qw/qr/k/vT (split, per-head layouts)
        k_qkv<<<dim3(1536/128, (T_*B_)/128), 256, SMEM_BIG>>>(
            p_hh, p_hl, p_qkvT_h + (size_t)i*1536*512, p_qkvT_l + (size_t)i*1536*512,
            rwb, rrb, nullptr, nullptr, nullptr, T_*B_, 1536, 512);
        // rk -> split bf16 [2048][512]
        k_rk<<<dim3(512/128, 2048/128), 256, SMEM_BIG>>>(
            p_posh, p_posl, p_rkT_h + (size_t)i*512*512, p_rkT_l + (size_t)i*512*512,
            nullptr, nullptr, nullptr, p_rkbf_h, p_rkbf_l, 2048, 512, 512);
        // fused attention: AC + E(shift) + mask + softmax + AV
        attn_fused<<<dim3(T_/64, B_*H_), 256, ATTN_SMEM_BYTES>>>(
            p_qw_h, p_qw_l, p_qr_h, p_qr_l, p_k_h, p_k_l,
            p_rkbf_h, p_rkbf_l, p_vth, p_vtl, p_pad, p_vech, p_vecl);
        // O proj
        k_f32<<<dim3(512/128, (T_*B_)/128), 256, SMEM_BIG>>>(
            p_vech, p_vecl, p_oT_h + (size_t)i*512*512, p_oT_l + (size_t)i*512*512,
            nullptr, nullptr, p_t1, nullptr, nullptr, T_*B_, 512, 512);
        // out1 = LN(h + attn)
        ln_kernel<<<T_*B_, 256>>>(p_h, p_t1, alg + i*D_, alb + i*D_, p_h, p_hh, p_hl,
                                  nullptr, nullptr, 0);
        // FF1
        k_ff1<<<dim3(DI_/128, (T_*B_)/128), 256, SMEM_BIG>>>(
            p_hh, p_hl, p_w1T_h + (size_t)i*2048*512, p_w1T_l + (size_t)i*2048*512,
            b1 + (size_t)i*DI_, nullptr, nullptr, p_ffh, p_ffl, T_*B_, DI_, 512);
        // FF2
        k_f32<<<dim3(512/128, (T_*B_)/128), 256, SMEM_BIG>>>(
            p_ffh, p_ffl, p_w2T_h + (size_t)i*512*2048, p_w2T_l + (size_t)i*512*2048,
            b2 + (size_t)i*D_, nullptr, p_t1, nullptr, nullptr, T_*B_, 512, DI_);
        // layer out = LN(out1 + ff)
        float* hb0 = out + (size_t)(2 + i) * BTD;
        float* hb1 = (i == L_ - 1) ? out : nullptr;
        ln_kernel<<<T_*B_, 256>>>(p_h, p_t1, flg + i*D_, flb + i*D_, p_h, p_hh, p_hl,
                                  hb0, hb1, 0);
    }
}